// round 4
// baseline (speedup 1.0000x reference)
#include <cuda_runtime.h>
#include <cuda_bf16.h>
#include <cstdint>

// ============================================================================
// CustomLSTM: B=32, T=2048, I=512, H=512 (4H=2048)
// Phase 1: gx = x@Wi^T + bi + bh  -- bf16x3 HMMA (mma.sync), 128x128 tiles.
// Phase 2: persistent scan, 128 CTAs x 4 hidden units. Wh A-fragments live in
//          registers for the whole scan; h exchanged as interleaved bf16
//          hi/lo uint2 pairs in global (direct LDG into B-fragments).
// NOTE: harness PTX target is compute_103 (no 'a') -> tcgen05 unavailable.
// ============================================================================

#define TT 2048
#define BB 32
#define II 512
#define HH 512
#define GG 2048

#define NC2 128                         // scan CTAs (one per 4 hidden units)

// ---------------- device scratch ----------------
__device__ float g_gx[(size_t)TT * BB * GG];     // 512 MB
__device__ uint2 g_hx[2][BB * 256];              // ping x [b][kpair] {hi2, lo2}
__device__ int   g_flags[NC2];

__device__ __forceinline__ float sigf(float x) { return 1.0f / (1.0f + __expf(-x)); }
__device__ __forceinline__ float tanh_fast(float x) {
    float r;
    asm("tanh.approx.f32 %0, %1;" : "=f"(r) : "f"(x));
    return r;
}

// pack two floats' bf16 parts; hi2 = {bf16(f1)|bf16(f0)}, lo2 = residuals
__device__ __forceinline__ void split_pair(float f0, float f1, uint32_t& hi2, uint32_t& lo2) {
    uint32_t h;
    asm("cvt.rn.bf16x2.f32 %0, %1, %2;" : "=r"(h) : "f"(f1), "f"(f0));
    float h0 = __uint_as_float(h << 16);
    float h1 = __uint_as_float(h & 0xFFFF0000u);
    asm("cvt.rn.bf16x2.f32 %0, %1, %2;" : "=r"(lo2) : "f"(f1 - h1), "f"(f0 - h0));
    hi2 = h;
}

__device__ __forceinline__ void mma_bf16(float* d, const uint32_t* a, const uint32_t* b) {
    asm volatile(
        "mma.sync.aligned.m16n8k16.row.col.f32.bf16.bf16.f32 "
        "{%0,%1,%2,%3}, {%4,%5,%6,%7}, {%8,%9}, {%0,%1,%2,%3};"
        : "+f"(d[0]), "+f"(d[1]), "+f"(d[2]), "+f"(d[3])
        : "r"(a[0]), "r"(a[1]), "r"(a[2]), "r"(a[3]), "r"(b[0]), "r"(b[1]));
}

// ============================================================================
// init: zero h ping buffer 0 and flags
// ============================================================================
__global__ void lstm_init_kernel() {
    int i = blockIdx.x * blockDim.x + threadIdx.x;
    if (i < BB * 256) g_hx[0][i] = make_uint2(0u, 0u);
    if (i < NC2) g_flags[i] = 0;
}

// ============================================================================
// Phase 1: gx[m=(t,b)][n=g] = x . Wi^T + bi + bh  (unchanged from R3, passing)
// ============================================================================
#define P1_ROWB 80
#define P1_OPB  (128 * P1_ROWB)
#define P1_BUFB (4 * P1_OPB)
#define P1_SMEM (2 * P1_BUFB + 512)

__global__ __launch_bounds__(256, 2) void gemm_gx_tc(
    const float* __restrict__ x, const float* __restrict__ Wi,
    const float* __restrict__ bi, const float* __restrict__ bh)
{
    extern __shared__ char sm[];
    float* bias_sm = reinterpret_cast<float*>(sm + 2 * P1_BUFB);

    const int tid = threadIdx.x;
    const int wid = tid >> 5;
    const int lane = tid & 31;
    const int g = lane >> 2;
    const int t4 = lane & 3;
    const int wm = wid >> 2;
    const int wn = wid & 3;

    const int gn0 = blockIdx.x * 128;
    const int gm0 = blockIdx.y * 128;

    if (tid < 128) bias_sm[tid] = bi[gn0 + tid] + bh[gn0 + tid];

    const float* asrc[4];
    const float* bsrc[4];
    uint32_t adst[4], bdst[4];
#pragma unroll
    for (int it = 0; it < 4; ++it) {
        int aidx = tid + it * 256;
        int row = aidx >> 3, q = aidx & 7;
        int m = gm0 + row;
        asrc[it] = x + ((size_t)(m & 31) * TT + (m >> 5)) * II + q * 4;
        adst[it] = row * P1_ROWB + q * 8;
        bsrc[it] = Wi + (size_t)(gn0 + row) * II + q * 4;
        bdst[it] = row * P1_ROWB + q * 8;
    }

    float acc[4][4][4];
#pragma unroll
    for (int a = 0; a < 4; ++a)
#pragma unroll
        for (int b = 0; b < 4; ++b)
#pragma unroll
            for (int c = 0; c < 4; ++c) acc[a][b][c] = 0.0f;

    float4 v[8];
#pragma unroll
    for (int it = 0; it < 4; ++it) {
        v[it]     = *reinterpret_cast<const float4*>(asrc[it]);
        v[4 + it] = *reinterpret_cast<const float4*>(bsrc[it]);
    }

    for (int kt = 0; kt < 16; ++kt) {
        char* buf = sm + (kt & 1) * P1_BUFB;
#pragma unroll
        for (int it = 0; it < 8; ++it) {
            float4 w = v[it];
            uint32_t h01, l01, h23, l23;
            split_pair(w.x, w.y, h01, l01);
            split_pair(w.z, w.w, h23, l23);
            char* dhi = buf + ((it < 4) ? adst[it] : (2 * P1_OPB + bdst[it - 4]));
            *reinterpret_cast<uint2*>(dhi) = make_uint2(h01, h23);
            *reinterpret_cast<uint2*>(dhi + P1_OPB) = make_uint2(l01, l23);
        }
        __syncthreads();

        if (kt < 15) {
            int ko = (kt + 1) * 32;
#pragma unroll
            for (int it = 0; it < 4; ++it) {
                v[it]     = *reinterpret_cast<const float4*>(asrc[it] + ko);
                v[4 + it] = *reinterpret_cast<const float4*>(bsrc[it] + ko);
            }
        }

        const char* Ah = buf;
        const char* Al = buf + P1_OPB;
        const char* Bh = buf + 2 * P1_OPB;
        const char* Bl = buf + 3 * P1_OPB;

#pragma unroll
        for (int ks = 0; ks < 2; ++ks) {
            const int kb = ks * 32 + 4 * t4;
            uint32_t bhf[4][2], blf[4][2];
#pragma unroll
            for (int nt = 0; nt < 4; ++nt) {
                int n = wn * 32 + nt * 8 + g;
                const char* ph = Bh + n * P1_ROWB + kb;
                const char* pl = Bl + n * P1_ROWB + kb;
                bhf[nt][0] = *reinterpret_cast<const uint32_t*>(ph);
                bhf[nt][1] = *reinterpret_cast<const uint32_t*>(ph + 16);
                blf[nt][0] = *reinterpret_cast<const uint32_t*>(pl);
                blf[nt][1] = *reinterpret_cast<const uint32_t*>(pl + 16);
            }
#pragma unroll
            for (int mt = 0; mt < 4; ++mt) {
                int r = wm * 64 + mt * 16 + g;
                const char* ph = Ah + r * P1_ROWB + kb;
                const char* pl = Al + r * P1_ROWB + kb;
                uint32_t ahf[4], alf[4];
                ahf[0] = *reinterpret_cast<const uint32_t*>(ph);
                ahf[1] = *reinterpret_cast<const uint32_t*>(ph + 8 * P1_ROWB);
                ahf[2] = *reinterpret_cast<const uint32_t*>(ph + 16);
                ahf[3] = *reinterpret_cast<const uint32_t*>(ph + 8 * P1_ROWB + 16);
                alf[0] = *reinterpret_cast<const uint32_t*>(pl);
                alf[1] = *reinterpret_cast<const uint32_t*>(pl + 8 * P1_ROWB);
                alf[2] = *reinterpret_cast<const uint32_t*>(pl + 16);
                alf[3] = *reinterpret_cast<const uint32_t*>(pl + 8 * P1_ROWB + 16);
#pragma unroll
                for (int nt = 0; nt < 4; ++nt) {
                    mma_bf16(acc[mt][nt], ahf, bhf[nt]);
                    mma_bf16(acc[mt][nt], ahf, blf[nt]);
                    mma_bf16(acc[mt][nt], alf, bhf[nt]);
                }
            }
        }
        __syncthreads();
    }

#pragma unroll
    for (int mt = 0; mt < 4; ++mt) {
        int m0 = gm0 + wm * 64 + mt * 16 + g;
#pragma unroll
        for (int nt = 0; nt < 4; ++nt) {
            int nl = wn * 32 + nt * 8 + 2 * t4;
            float b0v = bias_sm[nl], b1v = bias_sm[nl + 1];
            float2 u0 = make_float2(acc[mt][nt][0] + b0v, acc[mt][nt][1] + b1v);
            float2 u1 = make_float2(acc[mt][nt][2] + b0v, acc[mt][nt][3] + b1v);
            *reinterpret_cast<float2*>(&g_gx[(size_t)m0 * GG + gn0 + nl]) = u0;
            *reinterpret_cast<float2*>(&g_gx[(size_t)(m0 + 8) * GG + gn0 + nl]) = u1;
        }
    }
}

// ============================================================================
// Phase 2: persistent scan. 128 CTAs x 256 thr; CTA owns 4 hidden j
// (16 gate rows m). Warp w covers k chunk [w*64, w*64+64).
// A-fragments (Wh hi/lo) preloaded to registers; B (h) direct LDG.
// ============================================================================
__global__ __launch_bounds__(256, 1) void lstm_scan_tc(
    const float* __restrict__ Wh,
    float* __restrict__ y, float* __restrict__ hfin, float* __restrict__ cfin)
{
    __shared__ float part[8 * 16 * 36];        // 8 warp slabs, [m][36]
    __shared__ float hrow[BB * 4];             // [b][jj]

    const int tid = threadIdx.x;
    const int wid = tid >> 5;
    const int lane = tid & 31;
    const int g = lane >> 2;
    const int t4 = lane & 3;
    const int J0 = blockIdx.x * 4;
    const int kb = wid * 64;

    // ---- preload Wh A-fragments (hi/lo) into registers, once ----
    uint32_t ahf[4][4], alf[4][4];
    {
        const int m0 = g, m1 = g + 8;
        const int grow0 = (m0 >> 2) * 512 + J0 + (m0 & 3);
        const int grow1 = (m1 >> 2) * 512 + J0 + (m1 & 3);
#pragma unroll
        for (int ks = 0; ks < 4; ++ks) {
            int k0 = kb + ks * 16 + 2 * t4;
            float2 w00 = *reinterpret_cast<const float2*>(&Wh[(size_t)grow0 * HH + k0]);
            float2 w10 = *reinterpret_cast<const float2*>(&Wh[(size_t)grow1 * HH + k0]);
            float2 w01 = *reinterpret_cast<const float2*>(&Wh[(size_t)grow0 * HH + k0 + 8]);
            float2 w11 = *reinterpret_cast<const float2*>(&Wh[(size_t)grow1 * HH + k0 + 8]);
            split_pair(w00.x, w00.y, ahf[ks][0], alf[ks][0]);
            split_pair(w10.x, w10.y, ahf[ks][1], alf[ks][1]);
            split_pair(w01.x, w01.y, ahf[ks][2], alf[ks][2]);
            split_pair(w11.x, w11.y, ahf[ks][3], alf[ks][3]);
        }
    }

    // gate-thread mapping (tid < 128): hidden jj, batch b
    const int jj = (tid >> 5) & 3;
    const int b = tid & 31;

    float c_reg = 0.0f, h_last = 0.0f;
    volatile int* vflags = (volatile int*)g_flags;

    for (int t = 0; t < TT; ++t) {
        const int p = t & 1;

        // gx prefetch (independent of h; in flight during the wait)
        float gx0 = 0.f, gx1 = 0.f, gx2 = 0.f, gx3 = 0.f;
        if (tid < 128) {
            const float* gxp = g_gx + ((size_t)t * 32 + b) * GG + J0 + jj;
            gx0 = gxp[0];
            gx1 = gxp[512];
            gx2 = gxp[1024];
            gx3 = gxp[1536];
        }

        // ---- wait for h[t] from all CTAs ----
        if (t > 0) {
            if (tid < NC2) {
                while (vflags[tid] < t) __nanosleep(32);
            }
            __threadfence();   // acquire + L1D flush (CCTL.IVALL) for fresh h
        }
        __syncthreads();

        // ---- MMA: 16 gate rows x 32 batches, warp k-chunk 64, bf16x3 ----
        const uint2* __restrict__ hx = g_hx[p];
        float acc[4][4];
#pragma unroll
        for (int nt = 0; nt < 4; ++nt)
#pragma unroll
            for (int c = 0; c < 4; ++c) acc[nt][c] = 0.0f;

#pragma unroll
        for (int ks = 0; ks < 4; ++ks) {
            const int kp0 = (kb >> 1) + ks * 8 + t4;
#pragma unroll
            for (int nt = 0; nt < 4; ++nt) {
                const int n = nt * 8 + g;
                uint2 v0 = hx[n * 256 + kp0];
                uint2 v1 = hx[n * 256 + kp0 + 4];
                uint32_t bhf[2] = {v0.x, v1.x};
                uint32_t blf[2] = {v0.y, v1.y};
                mma_bf16(acc[nt], ahf[ks], bhf);
                mma_bf16(acc[nt], ahf[ks], blf);
                mma_bf16(acc[nt], alf[ks], bhf);
            }
        }

        // ---- partials to SMEM ----
        {
            float* slab = part + wid * (16 * 36);
#pragma unroll
            for (int nt = 0; nt < 4; ++nt) {
                int n = nt * 8 + 2 * t4;
                *reinterpret_cast<float2*>(&slab[g * 36 + n]) =
                    make_float2(acc[nt][0], acc[nt][1]);
                *reinterpret_cast<float2*>(&slab[(g + 8) * 36 + n]) =
                    make_float2(acc[nt][2], acc[nt][3]);
            }
        }
        __syncthreads();

        // ---- gate threads: reduce 8 slabs + gx, then cell update ----
        if (tid < 128) {
            float gate[4] = {gx0, gx1, gx2, gx3};
#pragma unroll
            for (int q = 0; q < 4; ++q) {
                const int m = q * 4 + jj;
#pragma unroll
                for (int w = 0; w < 8; ++w)
                    gate[q] += part[w * (16 * 36) + m * 36 + b];
            }
            float cn = sigf(gate[1]) * c_reg + sigf(gate[0]) * tanh_fast(gate[2]);
            float hn = sigf(gate[3]) * tanh_fast(cn);
            c_reg = cn;
            h_last = hn;
            hrow[b * 4 + jj] = hn;
        }
        __syncthreads();

        // ---- writers (warp 0): pack h -> global hi/lo pairs + y; publish ----
        if (tid < 32) {
            float4 h4 = *reinterpret_cast<const float4*>(&hrow[tid * 4]);
            uint32_t hi01, lo01, hi23, lo23;
            split_pair(h4.x, h4.y, hi01, lo01);
            split_pair(h4.z, h4.w, hi23, lo23);
            *reinterpret_cast<uint4*>(&g_hx[p ^ 1][tid * 256 + (J0 >> 1)]) =
                make_uint4(hi01, lo01, hi23, lo23);
            float* yp = y + ((size_t)tid * TT + t) * HH + J0;
            *reinterpret_cast<float4*>(yp) = h4;
            __syncwarp();
            if (tid == 0 && t < TT - 1) {
                __threadfence();
                vflags[blockIdx.x] = t + 1;
            }
        }
    }

    if (tid < 128) {
        hfin[(size_t)b * HH + J0 + jj] = h_last;
        cfin[(size_t)b * HH + J0 + jj] = c_reg;
    }
}

// ============================================================================
// launch
// ============================================================================
extern "C" void kernel_launch(void* const* d_in, const int* in_sizes, int n_in,
                              void* d_out, int out_size) {
    const float* x  = (const float*)d_in[0];
    const float* Wi = (const float*)d_in[1];
    const float* bi = (const float*)d_in[2];
    const float* Wh = (const float*)d_in[3];
    const float* bh = (const float*)d_in[4];

    float* y    = (float*)d_out;
    float* hfin = y + (size_t)BB * TT * HH;
    float* cfin = hfin + (size_t)BB * HH;

    cudaFuncSetAttribute(gemm_gx_tc,
                         cudaFuncAttributeMaxDynamicSharedMemorySize, P1_SMEM);

    lstm_init_kernel<<<32, 256>>>();
    gemm_gx_tc<<<dim3(16, 512), 256, P1_SMEM>>>(x, Wi, bi, bh);
    lstm_scan_tc<<<NC2, 256>>>(Wh, y, hfin, cfin);
}

// round 5
// speedup vs baseline: 1.4620x; 1.4620x over previous
#include <cuda_runtime.h>
#include <cuda_bf16.h>
#include <cstdint>

// ============================================================================
// CustomLSTM: B=32, T=2048, I=512, H=512 (4H=2048)
// Phase 1: gx = x@Wi^T + bi + bh  -- bf16x3 HMMA, 128x128 tiles.
//          Output stored TRANSPOSED as gx[t][g][b] for coalesced scan reads.
// Phase 2: persistent scan, 64 CTAs x 8 hidden units (R3-proven structure):
//          h ping-pong in global as bf16 hi/lo, bulk-coalesced copy to SMEM,
//          Wh A-fragments resident in REGISTERS, fused reduce+gate stage.
// NOTE: harness PTX target is compute_103 (no 'a') -> tcgen05 unavailable.
// ============================================================================

#define TT 2048
#define BB 32
#define II 512
#define HH 512
#define GG 2048

#define NCTA2 64                          // scan CTAs

// ---------------- device scratch ----------------
__device__ float g_gx[(size_t)TT * GG * BB];     // [t][g][b]  512 MB
__device__ uint4 g_hb[2][2][2048];               // ping x {hi,lo} x (b*64+kq)
__device__ int   g_flags[NCTA2];

__device__ __forceinline__ float sigf(float x) { return 1.0f / (1.0f + __expf(-x)); }
__device__ __forceinline__ float tanh_fast(float x) {
    float r;
    asm("tanh.approx.f32 %0, %1;" : "=f"(r) : "f"(x));
    return r;
}

// pack two floats' bf16 parts; hi2 = {bf16(f1)|bf16(f0)}, lo2 = residuals
__device__ __forceinline__ void split_pair(float f0, float f1, uint32_t& hi2, uint32_t& lo2) {
    uint32_t h;
    asm("cvt.rn.bf16x2.f32 %0, %1, %2;" : "=r"(h) : "f"(f1), "f"(f0));
    float h0 = __uint_as_float(h << 16);
    float h1 = __uint_as_float(h & 0xFFFF0000u);
    asm("cvt.rn.bf16x2.f32 %0, %1, %2;" : "=r"(lo2) : "f"(f1 - h1), "f"(f0 - h0));
    hi2 = h;
}

__device__ __forceinline__ void mma_bf16(float* d, const uint32_t* a, const uint32_t* b) {
    asm volatile(
        "mma.sync.aligned.m16n8k16.row.col.f32.bf16.bf16.f32 "
        "{%0,%1,%2,%3}, {%4,%5,%6,%7}, {%8,%9}, {%0,%1,%2,%3};"
        : "+f"(d[0]), "+f"(d[1]), "+f"(d[2]), "+f"(d[3])
        : "r"(a[0]), "r"(a[1]), "r"(a[2]), "r"(a[3]), "r"(b[0]), "r"(b[1]));
}

// ============================================================================
// init
// ============================================================================
__global__ void lstm_init_kernel() {
    int i = blockIdx.x * blockDim.x + threadIdx.x;
    if (i < 4096) g_hb[0][i >> 11][i & 2047] = make_uint4(0u, 0u, 0u, 0u);
    if (i < NCTA2) g_flags[i] = 0;
}

// ============================================================================
// Phase 1: bf16x3 HMMA GEMM (R3-proven), epilogue stores gx[t][g][b]
// ============================================================================
#define P1_ROWB 80
#define P1_OPB  (128 * P1_ROWB)
#define P1_BUFB (4 * P1_OPB)
#define P1_SMEM (2 * P1_BUFB + 512)

__global__ __launch_bounds__(256, 2) void gemm_gx_tc(
    const float* __restrict__ x, const float* __restrict__ Wi,
    const float* __restrict__ bi, const float* __restrict__ bh)
{
    extern __shared__ char sm[];
    float* bias_sm = reinterpret_cast<float*>(sm + 2 * P1_BUFB);

    const int tid = threadIdx.x;
    const int wid = tid >> 5;
    const int lane = tid & 31;
    const int g = lane >> 2;
    const int t4 = lane & 3;
    const int wm = wid >> 2;
    const int wn = wid & 3;

    const int gn0 = blockIdx.x * 128;
    const int gm0 = blockIdx.y * 128;

    if (tid < 128) bias_sm[tid] = bi[gn0 + tid] + bh[gn0 + tid];

    const float* asrc[4];
    const float* bsrc[4];
    uint32_t adst[4], bdst[4];
#pragma unroll
    for (int it = 0; it < 4; ++it) {
        int aidx = tid + it * 256;
        int row = aidx >> 3, q = aidx & 7;
        int m = gm0 + row;
        asrc[it] = x + ((size_t)(m & 31) * TT + (m >> 5)) * II + q * 4;
        adst[it] = row * P1_ROWB + q * 8;
        bsrc[it] = Wi + (size_t)(gn0 + row) * II + q * 4;
        bdst[it] = row * P1_ROWB + q * 8;
    }

    float acc[4][4][4];
#pragma unroll
    for (int a = 0; a < 4; ++a)
#pragma unroll
        for (int b = 0; b < 4; ++b)
#pragma unroll
            for (int c = 0; c < 4; ++c) acc[a][b][c] = 0.0f;

    float4 v[8];
#pragma unroll
    for (int it = 0; it < 4; ++it) {
        v[it]     = *reinterpret_cast<const float4*>(asrc[it]);
        v[4 + it] = *reinterpret_cast<const float4*>(bsrc[it]);
    }

    for (int kt = 0; kt < 16; ++kt) {
        char* buf = sm + (kt & 1) * P1_BUFB;
#pragma unroll
        for (int it = 0; it < 8; ++it) {
            float4 w = v[it];
            uint32_t h01, l01, h23, l23;
            split_pair(w.x, w.y, h01, l01);
            split_pair(w.z, w.w, h23, l23);
            char* dhi = buf + ((it < 4) ? adst[it] : (2 * P1_OPB + bdst[it - 4]));
            *reinterpret_cast<uint2*>(dhi) = make_uint2(h01, h23);
            *reinterpret_cast<uint2*>(dhi + P1_OPB) = make_uint2(l01, l23);
        }
        __syncthreads();

        if (kt < 15) {
            int ko = (kt + 1) * 32;
#pragma unroll
            for (int it = 0; it < 4; ++it) {
                v[it]     = *reinterpret_cast<const float4*>(asrc[it] + ko);
                v[4 + it] = *reinterpret_cast<const float4*>(bsrc[it] + ko);
            }
        }

        const char* Ah = buf;
        const char* Al = buf + P1_OPB;
        const char* Bh = buf + 2 * P1_OPB;
        const char* Bl = buf + 3 * P1_OPB;

#pragma unroll
        for (int ks = 0; ks < 2; ++ks) {
            const int kb = ks * 32 + 4 * t4;
            uint32_t bhf[4][2], blf[4][2];
#pragma unroll
            for (int nt = 0; nt < 4; ++nt) {
                int n = wn * 32 + nt * 8 + g;
                const char* ph = Bh + n * P1_ROWB + kb;
                const char* pl = Bl + n * P1_ROWB + kb;
                bhf[nt][0] = *reinterpret_cast<const uint32_t*>(ph);
                bhf[nt][1] = *reinterpret_cast<const uint32_t*>(ph + 16);
                blf[nt][0] = *reinterpret_cast<const uint32_t*>(pl);
                blf[nt][1] = *reinterpret_cast<const uint32_t*>(pl + 16);
            }
#pragma unroll
            for (int mt = 0; mt < 4; ++mt) {
                int r = wm * 64 + mt * 16 + g;
                const char* ph = Ah + r * P1_ROWB + kb;
                const char* pl = Al + r * P1_ROWB + kb;
                uint32_t ahf[4], alf[4];
                ahf[0] = *reinterpret_cast<const uint32_t*>(ph);
                ahf[1] = *reinterpret_cast<const uint32_t*>(ph + 8 * P1_ROWB);
                ahf[2] = *reinterpret_cast<const uint32_t*>(ph + 16);
                ahf[3] = *reinterpret_cast<const uint32_t*>(ph + 8 * P1_ROWB + 16);
                alf[0] = *reinterpret_cast<const uint32_t*>(pl);
                alf[1] = *reinterpret_cast<const uint32_t*>(pl + 8 * P1_ROWB);
                alf[2] = *reinterpret_cast<const uint32_t*>(pl + 16);
                alf[3] = *reinterpret_cast<const uint32_t*>(pl + 8 * P1_ROWB + 16);
#pragma unroll
                for (int nt = 0; nt < 4; ++nt) {
                    mma_bf16(acc[mt][nt], ahf, bhf[nt]);
                    mma_bf16(acc[mt][nt], ahf, blf[nt]);
                    mma_bf16(acc[mt][nt], alf, bhf[nt]);
                }
            }
        }
        __syncthreads();
    }

    // epilogue: transposed store gx[t][g][b]
#pragma unroll
    for (int mt = 0; mt < 4; ++mt) {
        int m0 = gm0 + wm * 64 + mt * 16 + g;
        int m1 = m0 + 8;
        size_t t0 = (size_t)(m0 >> 5), b0 = (size_t)(m0 & 31);
        size_t t1 = (size_t)(m1 >> 5), b1 = (size_t)(m1 & 31);
#pragma unroll
        for (int nt = 0; nt < 4; ++nt) {
            int nl = wn * 32 + nt * 8 + 2 * t4;
            size_t n = (size_t)(gn0 + nl);
            float bv0 = bias_sm[nl], bv1 = bias_sm[nl + 1];
            g_gx[(t0 * GG + n) * 32 + b0]       = acc[mt][nt][0] + bv0;
            g_gx[(t0 * GG + n + 1) * 32 + b0]   = acc[mt][nt][1] + bv1;
            g_gx[(t1 * GG + n) * 32 + b1]       = acc[mt][nt][2] + bv0;
            g_gx[(t1 * GG + n + 1) * 32 + b1]   = acc[mt][nt][3] + bv1;
        }
    }
}

// ============================================================================
// Phase 2: persistent scan. 64 CTAs x 256 thr; CTA owns 8 hidden j
// (32 gate rows). Warp w covers k-chunk [w*64, w*64+64).
// Wh A-fragments in registers; h staged via coalesced SMEM copy (R3 path).
// ============================================================================
#define WROW 1040                             // bytes per 512-bf16 row (+pad)
#define OFF_HS_HI 0
#define OFF_HS_LO (32 * WROW)                 // 33280
#define OFF_PART  (64 * WROW)                 // 66560
#define PART_SLABW (32 * 36)                  // floats per warp slab
#define OFF_HROW  (OFF_PART + 8 * PART_SLABW * 4)   // 103424
#define SCAN_SMEM (OFF_HROW + 32 * 9 * 4 + 64)      // ~104.6 KB

__global__ __launch_bounds__(256, 1) void lstm_scan_tc(
    const float* __restrict__ Wh,
    float* __restrict__ y, float* __restrict__ hfin, float* __restrict__ cfin)
{
    extern __shared__ char sm[];
    const int tid = threadIdx.x;
    const int wid = tid >> 5;
    const int lane = tid & 31;
    const int g = lane >> 2;
    const int t4 = lane & 3;
    const int J0 = blockIdx.x * 8;
    const int kb = wid * 64;

    // ---- preload Wh A-fragments into registers (once) ----
    // rows: m = mt*16 + g (+8); m -> gate q = m>>3, unit jj = m&7
    uint32_t ahf[2][4][4], alf[2][4][4];
#pragma unroll
    for (int mt = 0; mt < 2; ++mt) {
        int r0 = mt * 16 + g, r1 = r0 + 8;
        int grow0 = (r0 >> 3) * 512 + J0 + (r0 & 7);
        int grow1 = (r1 >> 3) * 512 + J0 + (r1 & 7);
#pragma unroll
        for (int ks = 0; ks < 4; ++ks) {
            int k0 = kb + ks * 16 + 2 * t4;
            float2 w00 = *reinterpret_cast<const float2*>(&Wh[(size_t)grow0 * HH + k0]);
            float2 w10 = *reinterpret_cast<const float2*>(&Wh[(size_t)grow1 * HH + k0]);
            float2 w01 = *reinterpret_cast<const float2*>(&Wh[(size_t)grow0 * HH + k0 + 8]);
            float2 w11 = *reinterpret_cast<const float2*>(&Wh[(size_t)grow1 * HH + k0 + 8]);
            split_pair(w00.x, w00.y, ahf[mt][ks][0], alf[mt][ks][0]);
            split_pair(w10.x, w10.y, ahf[mt][ks][1], alf[mt][ks][1]);
            split_pair(w01.x, w01.y, ahf[mt][ks][2], alf[mt][ks][2]);
            split_pair(w11.x, w11.y, ahf[mt][ks][3], alf[mt][ks][3]);
        }
    }

    // gate-thread mapping: hidden jj (0..7), batch b
    const int jj = tid >> 5;
    const int b = tid & 31;

    float c_reg = 0.0f, h_last = 0.0f;
    volatile int* vflags = (volatile int*)g_flags;

    for (int t = 0; t < TT; ++t) {
        const int p = t & 1;

        // gx prefetch (coalesced [t][g][b] layout; independent of h)
        const float* gxp = g_gx + ((size_t)t * GG + J0 + jj) * 32 + b;
        float gx0 = gxp[0];
        float gx1 = gxp[512 * 32];
        float gx2 = gxp[1024 * 32];
        float gx3 = gxp[1536 * 32];

        // ---- wait for h[t] from all CTAs ----
        if (t > 0) {
            if (tid < NCTA2) {
                while (vflags[tid] < t) __nanosleep(32);
            }
            __threadfence();
        }
        __syncthreads();

        // ---- bulk-coalesced copy h (hi/lo) global -> SMEM ----
#pragma unroll
        for (int it = 0; it < 16; ++it) {
            int idx = tid + it * 256;        // 0..4095
            int ver = idx >> 11;             // 0:hi 1:lo
            int c = idx & 2047;
            uint4 val = g_hb[p][ver][c];
            int bb = c >> 6, k0 = (c & 63) * 8;
            char* dst = sm + (ver ? OFF_HS_LO : OFF_HS_HI) + bb * WROW + k0 * 2;
            *reinterpret_cast<uint4*>(dst) = val;
        }
        __syncthreads();

        // ---- MMA: 32 gate rows x 32 batches, warp k-chunk 64, bf16x3 ----
        float acc[2][4][4];
#pragma unroll
        for (int a = 0; a < 2; ++a)
#pragma unroll
            for (int c2 = 0; c2 < 4; ++c2)
#pragma unroll
                for (int c = 0; c < 4; ++c) acc[a][c2][c] = 0.0f;

#pragma unroll
        for (int ks = 0; ks < 4; ++ks) {
            const int koff = (kb + ks * 16 + 2 * t4) * 2;
            uint32_t bhf[4][2], blf[4][2];
#pragma unroll
            for (int nt = 0; nt < 4; ++nt) {
                int n = nt * 8 + g;
                const char* ph = sm + OFF_HS_HI + n * WROW + koff;
                const char* pl = sm + OFF_HS_LO + n * WROW + koff;
                bhf[nt][0] = *reinterpret_cast<const uint32_t*>(ph);
                bhf[nt][1] = *reinterpret_cast<const uint32_t*>(ph + 16);
                blf[nt][0] = *reinterpret_cast<const uint32_t*>(pl);
                blf[nt][1] = *reinterpret_cast<const uint32_t*>(pl + 16);
            }
#pragma unroll
            for (int mt = 0; mt < 2; ++mt) {
#pragma unroll
                for (int nt = 0; nt < 4; ++nt) {
                    mma_bf16(acc[mt][nt], ahf[mt][ks], bhf[nt]);
                    mma_bf16(acc[mt][nt], ahf[mt][ks], blf[nt]);
                    mma_bf16(acc[mt][nt], alf[mt][ks], bhf[nt]);
                }
            }
        }

        // ---- partials to SMEM ----
        {
            float* slab = reinterpret_cast<float*>(sm + OFF_PART) + wid * PART_SLABW;
#pragma unroll
            for (int mt = 0; mt < 2; ++mt) {
                int m = mt * 16 + g;
#pragma unroll
                for (int nt = 0; nt < 4; ++nt) {
                    int n = nt * 8 + 2 * t4;
                    *reinterpret_cast<float2*>(&slab[m * 36 + n]) =
                        make_float2(acc[mt][nt][0], acc[mt][nt][1]);
                    *reinterpret_cast<float2*>(&slab[(m + 8) * 36 + n]) =
                        make_float2(acc[mt][nt][2], acc[mt][nt][3]);
                }
            }
        }
        __syncthreads();

        // ---- fused reduce + gate math: thread (jj, b) ----
        {
            const float* pbase = reinterpret_cast<const float*>(sm + OFF_PART);
            float gate[4] = {gx0, gx1, gx2, gx3};
#pragma unroll
            for (int q = 0; q < 4; ++q) {
                const int m = q * 8 + jj;
#pragma unroll
                for (int w = 0; w < 8; ++w)
                    gate[q] += pbase[w * PART_SLABW + m * 36 + b];
            }
            float cn = sigf(gate[1]) * c_reg + sigf(gate[0]) * tanh_fast(gate[2]);
            float hn = sigf(gate[3]) * tanh_fast(cn);
            c_reg = cn;
            h_last = hn;
            reinterpret_cast<float*>(sm + OFF_HROW)[b * 9 + jj] = hn;
        }
        __syncthreads();

        // ---- writers (warp 0): pack h -> global hi/lo + y; publish flag ----
        if (tid < 32) {
            const float* hr = reinterpret_cast<const float*>(sm + OFF_HROW) + tid * 9;
            float h0 = hr[0], h1 = hr[1], h2 = hr[2], h3 = hr[3];
            float h4 = hr[4], h5 = hr[5], h6 = hr[6], h7 = hr[7];
            uint32_t hi01, lo01, hi23, lo23, hi45, lo45, hi67, lo67;
            split_pair(h0, h1, hi01, lo01);
            split_pair(h2, h3, hi23, lo23);
            split_pair(h4, h5, hi45, lo45);
            split_pair(h6, h7, hi67, lo67);
            int ci = tid * 64 + (J0 >> 3);
            g_hb[p ^ 1][0][ci] = make_uint4(hi01, hi23, hi45, hi67);
            g_hb[p ^ 1][1][ci] = make_uint4(lo01, lo23, lo45, lo67);
            float* yp = y + ((size_t)tid * TT + t) * HH + J0;
            *reinterpret_cast<float4*>(yp)     = make_float4(h0, h1, h2, h3);
            *reinterpret_cast<float4*>(yp + 4) = make_float4(h4, h5, h6, h7);
            __syncwarp();
            if (tid == 0 && t < TT - 1) {
                __threadfence();
                vflags[blockIdx.x] = t + 1;
            }
        }
    }

    hfin[(size_t)b * HH + J0 + jj] = h_last;
    cfin[(size_t)b * HH + J0 + jj] = c_reg;
}

// ============================================================================
// launch
// ============================================================================
extern "C" void kernel_launch(void* const* d_in, const int* in_sizes, int n_in,
                              void* d_out, int out_size) {
    const float* x  = (const float*)d_in[0];
    const float* Wi = (const float*)d_in[1];
    const float* bi = (const float*)d_in[2];
    const float* Wh = (const float*)d_in[3];
    const float* bh = (const float*)d_in[4];

    float* y    = (float*)d_out;
    float* hfin = y + (size_t)BB * TT * HH;
    float* cfin = hfin + (size_t)BB * HH;

    cudaFuncSetAttribute(gemm_gx_tc,
                         cudaFuncAttributeMaxDynamicSharedMemorySize, P1_SMEM);
    cudaFuncSetAttribute(lstm_scan_tc,
                         cudaFuncAttributeMaxDynamicSharedMemorySize, SCAN_SMEM);

    lstm_init_kernel<<<32, 256>>>();
    gemm_gx_tc<<<dim3(16, 512), 256, P1_SMEM>>>(x, Wi, bi, bh);
    lstm_scan_tc<<<NCTA2, 256, SCAN_SMEM>>>(Wh, y, hfin, cfin);
}

// round 6
// speedup vs baseline: 1.5473x; 1.0584x over previous
#include <cuda_runtime.h>
#include <cuda_bf16.h>
#include <cstdint>

// ============================================================================
// CustomLSTM: B=32, T=2048, I=512, H=512 (4H=2048)
// Phase 1: gx = x@Wi^T + bi + bh  -- bf16x3 HMMA, 128x128 tiles.
//          Output stored TRANSPOSED as gx[t][g][b]; epilogue stages the tile
//          through SMEM so global stores are fully coalesced 128B rows.
// Phase 2: persistent scan, 64 CTAs x 8 hidden units; h ping-pong in global
//          as bf16 hi/lo, coalesced SMEM staging, Wh A-frags in registers,
//          fused reduce+gate stage. (R5 scan, unchanged.)
// NOTE: harness PTX target is compute_103 (no 'a') -> tcgen05 unavailable.
// ============================================================================

#define TT 2048
#define BB 32
#define II 512
#define HH 512
#define GG 2048

#define NCTA2 64                          // scan CTAs

// ---------------- device scratch ----------------
__device__ float g_gx[(size_t)TT * GG * BB];     // [t][g][b]  512 MB
__device__ uint4 g_hb[2][2][2048];               // ping x {hi,lo} x (b*64+kq)
__device__ int   g_flags[NCTA2];

__device__ __forceinline__ float sigf(float x) { return 1.0f / (1.0f + __expf(-x)); }
__device__ __forceinline__ float tanh_fast(float x) {
    float r;
    asm("tanh.approx.f32 %0, %1;" : "=f"(r) : "f"(x));
    return r;
}

// pack two floats' bf16 parts; hi2 = {bf16(f1)|bf16(f0)}, lo2 = residuals
__device__ __forceinline__ void split_pair(float f0, float f1, uint32_t& hi2, uint32_t& lo2) {
    uint32_t h;
    asm("cvt.rn.bf16x2.f32 %0, %1, %2;" : "=r"(h) : "f"(f1), "f"(f0));
    float h0 = __uint_as_float(h << 16);
    float h1 = __uint_as_float(h & 0xFFFF0000u);
    asm("cvt.rn.bf16x2.f32 %0, %1, %2;" : "=r"(lo2) : "f"(f1 - h1), "f"(f0 - h0));
    hi2 = h;
}

__device__ __forceinline__ void mma_bf16(float* d, const uint32_t* a, const uint32_t* b) {
    asm volatile(
        "mma.sync.aligned.m16n8k16.row.col.f32.bf16.bf16.f32 "
        "{%0,%1,%2,%3}, {%4,%5,%6,%7}, {%8,%9}, {%0,%1,%2,%3};"
        : "+f"(d[0]), "+f"(d[1]), "+f"(d[2]), "+f"(d[3])
        : "r"(a[0]), "r"(a[1]), "r"(a[2]), "r"(a[3]), "r"(b[0]), "r"(b[1]));
}

// ============================================================================
// init
// ============================================================================
__global__ void lstm_init_kernel() {
    int i = blockIdx.x * blockDim.x + threadIdx.x;
    if (i < 4096) g_hb[0][i >> 11][i & 2047] = make_uint4(0u, 0u, 0u, 0u);
    if (i < NCTA2) g_flags[i] = 0;
}

// ============================================================================
// Phase 1: bf16x3 HMMA GEMM; SMEM-staged transposed epilogue
// ============================================================================
#define P1_ROWB 80
#define P1_OPB  (128 * P1_ROWB)
#define P1_BUFB (4 * P1_OPB)
#define P1_SMEM (2 * P1_BUFB + 512)
#define EPI_STRIDE 36                      // floats per [t][n] row in staging

__global__ __launch_bounds__(256, 2) void gemm_gx_tc(
    const float* __restrict__ x, const float* __restrict__ Wi,
    const float* __restrict__ bi, const float* __restrict__ bh)
{
    extern __shared__ char sm[];
    float* bias_sm = reinterpret_cast<float*>(sm + 2 * P1_BUFB);

    const int tid = threadIdx.x;
    const int wid = tid >> 5;
    const int lane = tid & 31;
    const int g = lane >> 2;
    const int t4 = lane & 3;
    const int wm = wid >> 2;
    const int wn = wid & 3;

    const int gn0 = blockIdx.x * 128;
    const int gm0 = blockIdx.y * 128;

    if (tid < 128) bias_sm[tid] = bi[gn0 + tid] + bh[gn0 + tid];

    const float* asrc[4];
    const float* bsrc[4];
    uint32_t adst[4], bdst[4];
#pragma unroll
    for (int it = 0; it < 4; ++it) {
        int aidx = tid + it * 256;
        int row = aidx >> 3, q = aidx & 7;
        int m = gm0 + row;
        asrc[it] = x + ((size_t)(m & 31) * TT + (m >> 5)) * II + q * 4;
        adst[it] = row * P1_ROWB + q * 8;
        bsrc[it] = Wi + (size_t)(gn0 + row) * II + q * 4;
        bdst[it] = row * P1_ROWB + q * 8;
    }

    float acc[4][4][4];
#pragma unroll
    for (int a = 0; a < 4; ++a)
#pragma unroll
        for (int b = 0; b < 4; ++b)
#pragma unroll
            for (int c = 0; c < 4; ++c) acc[a][b][c] = 0.0f;

    float4 v[8];
#pragma unroll
    for (int it = 0; it < 4; ++it) {
        v[it]     = *reinterpret_cast<const float4*>(asrc[it]);
        v[4 + it] = *reinterpret_cast<const float4*>(bsrc[it]);
    }

    for (int kt = 0; kt < 16; ++kt) {
        char* buf = sm + (kt & 1) * P1_BUFB;
#pragma unroll
        for (int it = 0; it < 8; ++it) {
            float4 w = v[it];
            uint32_t h01, l01, h23, l23;
            split_pair(w.x, w.y, h01, l01);
            split_pair(w.z, w.w, h23, l23);
            char* dhi = buf + ((it < 4) ? adst[it] : (2 * P1_OPB + bdst[it - 4]));
            *reinterpret_cast<uint2*>(dhi) = make_uint2(h01, h23);
            *reinterpret_cast<uint2*>(dhi + P1_OPB) = make_uint2(l01, l23);
        }
        __syncthreads();

        if (kt < 15) {
            int ko = (kt + 1) * 32;
#pragma unroll
            for (int it = 0; it < 4; ++it) {
                v[it]     = *reinterpret_cast<const float4*>(asrc[it] + ko);
                v[4 + it] = *reinterpret_cast<const float4*>(bsrc[it] + ko);
            }
        }

        const char* Ah = buf;
        const char* Al = buf + P1_OPB;
        const char* Bh = buf + 2 * P1_OPB;
        const char* Bl = buf + 3 * P1_OPB;

#pragma unroll
        for (int ks = 0; ks < 2; ++ks) {
            const int kb = ks * 32 + 4 * t4;
            uint32_t bhf[4][2], blf[4][2];
#pragma unroll
            for (int nt = 0; nt < 4; ++nt) {
                int n = wn * 32 + nt * 8 + g;
                const char* ph = Bh + n * P1_ROWB + kb;
                const char* pl = Bl + n * P1_ROWB + kb;
                bhf[nt][0] = *reinterpret_cast<const uint32_t*>(ph);
                bhf[nt][1] = *reinterpret_cast<const uint32_t*>(ph + 16);
                blf[nt][0] = *reinterpret_cast<const uint32_t*>(pl);
                blf[nt][1] = *reinterpret_cast<const uint32_t*>(pl + 16);
            }
#pragma unroll
            for (int mt = 0; mt < 4; ++mt) {
                int r = wm * 64 + mt * 16 + g;
                const char* ph = Ah + r * P1_ROWB + kb;
                const char* pl = Al + r * P1_ROWB + kb;
                uint32_t ahf[4], alf[4];
                ahf[0] = *reinterpret_cast<const uint32_t*>(ph);
                ahf[1] = *reinterpret_cast<const uint32_t*>(ph + 8 * P1_ROWB);
                ahf[2] = *reinterpret_cast<const uint32_t*>(ph + 16);
                ahf[3] = *reinterpret_cast<const uint32_t*>(ph + 8 * P1_ROWB + 16);
                alf[0] = *reinterpret_cast<const uint32_t*>(pl);
                alf[1] = *reinterpret_cast<const uint32_t*>(pl + 8 * P1_ROWB);
                alf[2] = *reinterpret_cast<const uint32_t*>(pl + 16);
                alf[3] = *reinterpret_cast<const uint32_t*>(pl + 8 * P1_ROWB + 16);
#pragma unroll
                for (int nt = 0; nt < 4; ++nt) {
                    mma_bf16(acc[mt][nt], ahf, bhf[nt]);
                    mma_bf16(acc[mt][nt], ahf, blf[nt]);
                    mma_bf16(acc[mt][nt], alf, bhf[nt]);
                }
            }
        }
        __syncthreads();
    }

    // ---- epilogue: stage [tloc][n][b] tile in SMEM, then coalesced STG ----
    // staging buffer reuses the (now dead) double buffers: 4*128*36*4 = 73728 B
    float* stage = reinterpret_cast<float*>(sm);
#pragma unroll
    for (int mt = 0; mt < 4; ++mt) {
        int lm0 = wm * 64 + mt * 16 + g;      // 0..127
        int lm1 = lm0 + 8;
        int tl0 = lm0 >> 5, bb0 = lm0 & 31;
        int tl1 = lm1 >> 5, bb1 = lm1 & 31;
#pragma unroll
        for (int nt = 0; nt < 4; ++nt) {
            int nl = wn * 32 + nt * 8 + 2 * t4;
            float bv0 = bias_sm[nl], bv1 = bias_sm[nl + 1];
            stage[(tl0 * 128 + nl) * EPI_STRIDE + bb0]       = acc[mt][nt][0] + bv0;
            stage[(tl0 * 128 + nl + 1) * EPI_STRIDE + bb0]   = acc[mt][nt][1] + bv1;
            stage[(tl1 * 128 + nl) * EPI_STRIDE + bb1]       = acc[mt][nt][2] + bv0;
            stage[(tl1 * 128 + nl + 1) * EPI_STRIDE + bb1]   = acc[mt][nt][3] + bv1;
        }
    }
    __syncthreads();

    // write-out: 512 rows x 32 floats, 8 lanes of float4 per row
    const size_t tbase = (size_t)(gm0 >> 5);   // 4 consecutive t values
#pragma unroll
    for (int it = 0; it < 16; ++it) {
        int i = tid + it * 256;                // 0..4095
        int row = i >> 3;                      // 0..511 = tloc*128 + n
        int q = i & 7;
        int tloc = row >> 7, n = row & 127;
        float4 val = *reinterpret_cast<const float4*>(&stage[row * EPI_STRIDE + q * 4]);
        float* dst = g_gx + ((tbase + tloc) * GG + gn0 + n) * 32 + q * 4;
        *reinterpret_cast<float4*>(dst) = val;
    }
}

// ============================================================================
// Phase 2: persistent scan (R5, unchanged)
// ============================================================================
#define WROW 1040
#define OFF_HS_HI 0
#define OFF_HS_LO (32 * WROW)
#define OFF_PART  (64 * WROW)
#define PART_SLABW (32 * 36)
#define OFF_HROW  (OFF_PART + 8 * PART_SLABW * 4)
#define SCAN_SMEM (OFF_HROW + 32 * 9 * 4 + 64)

__global__ __launch_bounds__(256, 1) void lstm_scan_tc(
    const float* __restrict__ Wh,
    float* __restrict__ y, float* __restrict__ hfin, float* __restrict__ cfin)
{
    extern __shared__ char sm[];
    const int tid = threadIdx.x;
    const int wid = tid >> 5;
    const int lane = tid & 31;
    const int g = lane >> 2;
    const int t4 = lane & 3;
    const int J0 = blockIdx.x * 8;
    const int kb = wid * 64;

    // ---- preload Wh A-fragments into registers (once) ----
    uint32_t ahf[2][4][4], alf[2][4][4];
#pragma unroll
    for (int mt = 0; mt < 2; ++mt) {
        int r0 = mt * 16 + g, r1 = r0 + 8;
        int grow0 = (r0 >> 3) * 512 + J0 + (r0 & 7);
        int grow1 = (r1 >> 3) * 512 + J0 + (r1 & 7);
#pragma unroll
        for (int ks = 0; ks < 4; ++ks) {
            int k0 = kb + ks * 16 + 2 * t4;
            float2 w00 = *reinterpret_cast<const float2*>(&Wh[(size_t)grow0 * HH + k0]);
            float2 w10 = *reinterpret_cast<const float2*>(&Wh[(size_t)grow1 * HH + k0]);
            float2 w01 = *reinterpret_cast<const float2*>(&Wh[(size_t)grow0 * HH + k0 + 8]);
            float2 w11 = *reinterpret_cast<const float2*>(&Wh[(size_t)grow1 * HH + k0 + 8]);
            split_pair(w00.x, w00.y, ahf[mt][ks][0], alf[mt][ks][0]);
            split_pair(w10.x, w10.y, ahf[mt][ks][1], alf[mt][ks][1]);
            split_pair(w01.x, w01.y, ahf[mt][ks][2], alf[mt][ks][2]);
            split_pair(w11.x, w11.y, ahf[mt][ks][3], alf[mt][ks][3]);
        }
    }

    const int jj = tid >> 5;
    const int b = tid & 31;

    float c_reg = 0.0f, h_last = 0.0f;
    volatile int* vflags = (volatile int*)g_flags;

    for (int t = 0; t < TT; ++t) {
        const int p = t & 1;

        const float* gxp = g_gx + ((size_t)t * GG + J0 + jj) * 32 + b;
        float gx0 = gxp[0];
        float gx1 = gxp[512 * 32];
        float gx2 = gxp[1024 * 32];
        float gx3 = gxp[1536 * 32];

        if (t > 0) {
            if (tid < NCTA2) {
                while (vflags[tid] < t) __nanosleep(32);
            }
            __threadfence();
        }
        __syncthreads();

#pragma unroll
        for (int it = 0; it < 16; ++it) {
            int idx = tid + it * 256;
            int ver = idx >> 11;
            int c = idx & 2047;
            uint4 val = g_hb[p][ver][c];
            int bb = c >> 6, k0 = (c & 63) * 8;
            char* dst = sm + (ver ? OFF_HS_LO : OFF_HS_HI) + bb * WROW + k0 * 2;
            *reinterpret_cast<uint4*>(dst) = val;
        }
        __syncthreads();

        float acc[2][4][4];
#pragma unroll
        for (int a = 0; a < 2; ++a)
#pragma unroll
            for (int c2 = 0; c2 < 4; ++c2)
#pragma unroll
                for (int c = 0; c < 4; ++c) acc[a][c2][c] = 0.0f;

#pragma unroll
        for (int ks = 0; ks < 4; ++ks) {
            const int koff = (kb + ks * 16 + 2 * t4) * 2;
            uint32_t bhf[4][2], blf[4][2];
#pragma unroll
            for (int nt = 0; nt < 4; ++nt) {
                int n = nt * 8 + g;
                const char* ph = sm + OFF_HS_HI + n * WROW + koff;
                const char* pl = sm + OFF_HS_LO + n * WROW + koff;
                bhf[nt][0] = *reinterpret_cast<const uint32_t*>(ph);
                bhf[nt][1] = *reinterpret_cast<const uint32_t*>(ph + 16);
                blf[nt][0] = *reinterpret_cast<const uint32_t*>(pl);
                blf[nt][1] = *reinterpret_cast<const uint32_t*>(pl + 16);
            }
#pragma unroll
            for (int mt = 0; mt < 2; ++mt) {
#pragma unroll
                for (int nt = 0; nt < 4; ++nt) {
                    mma_bf16(acc[mt][nt], ahf[mt][ks], bhf[nt]);
                    mma_bf16(acc[mt][nt], ahf[mt][ks], blf[nt]);
                    mma_bf16(acc[mt][nt], alf[mt][ks], bhf[nt]);
                }
            }
        }

        {
            float* slab = reinterpret_cast<float*>(sm + OFF_PART) + wid * PART_SLABW;
#pragma unroll
            for (int mt = 0; mt < 2; ++mt) {
                int m = mt * 16 + g;
#pragma unroll
                for (int nt = 0; nt < 4; ++nt) {
                    int n = nt * 8 + 2 * t4;
                    *reinterpret_cast<float2*>(&slab[m * 36 + n]) =
                        make_float2(acc[mt][nt][0], acc[mt][nt][1]);
                    *reinterpret_cast<float2*>(&slab[(m + 8) * 36 + n]) =
                        make_float2(acc[mt][nt][2], acc[mt][nt][3]);
                }
            }
        }
        __syncthreads();

        {
            const float* pbase = reinterpret_cast<const float*>(sm + OFF_PART);
            float gate[4] = {gx0, gx1, gx2, gx3};
#pragma unroll
            for (int q = 0; q < 4; ++q) {
                const int m = q * 8 + jj;
#pragma unroll
                for (int w = 0; w < 8; ++w)
                    gate[q] += pbase[w * PART_SLABW + m * 36 + b];
            }
            float cn = sigf(gate[1]) * c_reg + sigf(gate[0]) * tanh_fast(gate[2]);
            float hn = sigf(gate[3]) * tanh_fast(cn);
            c_reg = cn;
            h_last = hn;
            reinterpret_cast<float*>(sm + OFF_HROW)[b * 9 + jj] = hn;
        }
        __syncthreads();

        if (tid < 32) {
            const float* hr = reinterpret_cast<const float*>(sm + OFF_HROW) + tid * 9;
            float h0 = hr[0], h1 = hr[1], h2 = hr[2], h3 = hr[3];
            float h4 = hr[4], h5 = hr[5], h6 = hr[6], h7 = hr[7];
            uint32_t hi01, lo01, hi23, lo23, hi45, lo45, hi67, lo67;
            split_pair(h0, h1, hi01, lo01);
            split_pair(h2, h3, hi23, lo23);
            split_pair(h4, h5, hi45, lo45);
            split_pair(h6, h7, hi67, lo67);
            int ci = tid * 64 + (J0 >> 3);
            g_hb[p ^ 1][0][ci] = make_uint4(hi01, hi23, hi45, hi67);
            g_hb[p ^ 1][1][ci] = make_uint4(lo01, lo23, lo45, lo67);
            float* yp = y + ((size_t)tid * TT + t) * HH + J0;
            *reinterpret_cast<float4*>(yp)     = make_float4(h0, h1, h2, h3);
            *reinterpret_cast<float4*>(yp + 4) = make_float4(h4, h5, h6, h7);
            __syncwarp();
            if (tid == 0 && t < TT - 1) {
                __threadfence();
                vflags[blockIdx.x] = t + 1;
            }
        }
    }

    hfin[(size_t)b * HH + J0 + jj] = h_last;
    cfin[(size_t)b * HH + J0 + jj] = c_reg;
}

// ============================================================================
// launch
// ============================================================================
extern "C" void kernel_launch(void* const* d_in, const int* in_sizes, int n_in,
                              void* d_out, int out_size) {
    const float* x  = (const float*)d_in[0];
    const float* Wi = (const float*)d_in[1];
    const float* bi = (const float*)d_in[2];
    const float* Wh = (const float*)d_in[3];
    const float* bh = (const float*)d_in[4];

    float* y    = (float*)d_out;
    float* hfin = y + (size_t)BB * TT * HH;
    float* cfin = hfin + (size_t)BB * HH;

    cudaFuncSetAttribute(gemm_gx_tc,
                         cudaFuncAttributeMaxDynamicSharedMemorySize, P1_SMEM);
    cudaFuncSetAttribute(lstm_scan_tc,
                         cudaFuncAttributeMaxDynamicSharedMemorySize, SCAN_SMEM);

    lstm_init_kernel<<<32, 256>>>();
    gemm_gx_tc<<<dim3(16, 512), 256, P1_SMEM>>>(x, Wi, bi, bh);
    lstm_scan_tc<<<NCTA2, 256, SCAN_SMEM>>>(Wh, y, hfin, cfin);
}

// round 8
// speedup vs baseline: 1.5996x; 1.0338x over previous
#include <cuda_runtime.h>
#include <cuda_bf16.h>
#include <cstdint>

// ============================================================================
// CustomLSTM: B=32, T=2048, I=512, H=512 (4H=2048)
// Phase 1: gx = x@Wi^T + bi + bh  -- bf16x3 HMMA, 128x128 tiles, SMEM-staged
//          transposed epilogue -> gx[t][g][b]. Init folded into block (0,0).
// Phase 2: persistent scan, 64 CTAs. Warp 0 polls flags (acquire + nanosleep),
//          bar broadcasts; per-warp h slice copy via .cg (no L1 flush);
//          3 CTA barriers/step; Wh A-frags in registers; bf16x3 HMMA.
// NOTE: harness PTX target is compute_103 (no 'a') -> tcgen05 unavailable.
// ============================================================================

#define TT 2048
#define BB 32
#define II 512
#define HH 512
#define GG 2048

#define NCTA2 64

// ---------------- device scratch ----------------
__device__ float g_gx[(size_t)TT * GG * BB];     // [t][g][b]  512 MB
__device__ uint4 g_hb[2][2][2048];               // ping x {hi,lo} x (b*64+kq)
__device__ int   g_flags[NCTA2];

__device__ __forceinline__ float sigf(float x) { return 1.0f / (1.0f + __expf(-x)); }
__device__ __forceinline__ float tanh_fast(float x) {
    float r;
    asm("tanh.approx.f32 %0, %1;" : "=f"(r) : "f"(x));
    return r;
}
// acquire flag load: HW-orders subsequent loads after it; "memory" clobber
// stops the compiler moving the h-loads above the spin.
__device__ __forceinline__ int ldflag_acq(const int* p) {
    int v;
    asm volatile("ld.acquire.gpu.global.b32 %0, [%1];" : "=r"(v) : "l"(p) : "memory");
    return v;
}

// pack two floats' bf16 parts; hi2 = {bf16(f1)|bf16(f0)}, lo2 = residuals
__device__ __forceinline__ void split_pair(float f0, float f1, uint32_t& hi2, uint32_t& lo2) {
    uint32_t h;
    asm("cvt.rn.bf16x2.f32 %0, %1, %2;" : "=r"(h) : "f"(f1), "f"(f0));
    float h0 = __uint_as_float(h << 16);
    float h1 = __uint_as_float(h & 0xFFFF0000u);
    asm("cvt.rn.bf16x2.f32 %0, %1, %2;" : "=r"(lo2) : "f"(f1 - h1), "f"(f0 - h0));
    hi2 = h;
}

__device__ __forceinline__ void mma_bf16(float* d, const uint32_t* a, const uint32_t* b) {
    asm volatile(
        "mma.sync.aligned.m16n8k16.row.col.f32.bf16.bf16.f32 "
        "{%0,%1,%2,%3}, {%4,%5,%6,%7}, {%8,%9}, {%0,%1,%2,%3};"
        : "+f"(d[0]), "+f"(d[1]), "+f"(d[2]), "+f"(d[3])
        : "r"(a[0]), "r"(a[1]), "r"(a[2]), "r"(a[3]), "r"(b[0]), "r"(b[1]));
}

// ============================================================================
// Phase 1: bf16x3 HMMA GEMM; SMEM-staged transposed epilogue; init fold
// ============================================================================
#define P1_ROWB 80
#define P1_OPB  (128 * P1_ROWB)
#define P1_BUFB (4 * P1_OPB)
#define P1_SMEM (2 * P1_BUFB + 512)
#define EPI_STRIDE 36

__global__ __launch_bounds__(256, 2) void gemm_gx_tc(
    const float* __restrict__ x, const float* __restrict__ Wi,
    const float* __restrict__ bi, const float* __restrict__ bh)
{
    extern __shared__ char sm[];
    float* bias_sm = reinterpret_cast<float*>(sm + 2 * P1_BUFB);

    const int tid = threadIdx.x;
    const int wid = tid >> 5;
    const int lane = tid & 31;
    const int g = lane >> 2;
    const int t4 = lane & 3;
    const int wm = wid >> 2;
    const int wn = wid & 3;

    const int gn0 = blockIdx.x * 128;
    const int gm0 = blockIdx.y * 128;

    // ---- folded init (block 0,0): zero h ping 0 and flags ----
    if (blockIdx.x == 0 && blockIdx.y == 0) {
#pragma unroll
        for (int it = 0; it < 16; ++it) {
            int i = tid + it * 256;
            g_hb[0][i >> 11][i & 2047] = make_uint4(0u, 0u, 0u, 0u);
        }
        if (tid < NCTA2) g_flags[tid] = 0;
    }

    if (tid < 128) bias_sm[tid] = bi[gn0 + tid] + bh[gn0 + tid];

    const float* asrc[4];
    const float* bsrc[4];
    uint32_t adst[4], bdst[4];
#pragma unroll
    for (int it = 0; it < 4; ++it) {
        int aidx = tid + it * 256;
        int row = aidx >> 3, q = aidx & 7;
        int m = gm0 + row;
        asrc[it] = x + ((size_t)(m & 31) * TT + (m >> 5)) * II + q * 4;
        adst[it] = row * P1_ROWB + q * 8;
        bsrc[it] = Wi + (size_t)(gn0 + row) * II + q * 4;
        bdst[it] = row * P1_ROWB + q * 8;
    }

    float acc[4][4][4];
#pragma unroll
    for (int a = 0; a < 4; ++a)
#pragma unroll
        for (int b = 0; b < 4; ++b)
#pragma unroll
            for (int c = 0; c < 4; ++c) acc[a][b][c] = 0.0f;

    float4 v[8];
#pragma unroll
    for (int it = 0; it < 4; ++it) {
        v[it]     = *reinterpret_cast<const float4*>(asrc[it]);
        v[4 + it] = *reinterpret_cast<const float4*>(bsrc[it]);
    }

    for (int kt = 0; kt < 16; ++kt) {
        char* buf = sm + (kt & 1) * P1_BUFB;
#pragma unroll
        for (int it = 0; it < 8; ++it) {
            float4 w = v[it];
            uint32_t h01, l01, h23, l23;
            split_pair(w.x, w.y, h01, l01);
            split_pair(w.z, w.w, h23, l23);
            char* dhi = buf + ((it < 4) ? adst[it] : (2 * P1_OPB + bdst[it - 4]));
            *reinterpret_cast<uint2*>(dhi) = make_uint2(h01, h23);
            *reinterpret_cast<uint2*>(dhi + P1_OPB) = make_uint2(l01, l23);
        }
        __syncthreads();

        if (kt < 15) {
            int ko = (kt + 1) * 32;
#pragma unroll
            for (int it = 0; it < 4; ++it) {
                v[it]     = *reinterpret_cast<const float4*>(asrc[it] + ko);
                v[4 + it] = *reinterpret_cast<const float4*>(bsrc[it] + ko);
            }
        }

        const char* Ah = buf;
        const char* Al = buf + P1_OPB;
        const char* Bh = buf + 2 * P1_OPB;
        const char* Bl = buf + 3 * P1_OPB;

#pragma unroll
        for (int ks = 0; ks < 2; ++ks) {
            const int kb = ks * 32 + 4 * t4;
            uint32_t bhf[4][2], blf[4][2];
#pragma unroll
            for (int nt = 0; nt < 4; ++nt) {
                int n = wn * 32 + nt * 8 + g;
                const char* ph = Bh + n * P1_ROWB + kb;
                const char* pl = Bl + n * P1_ROWB + kb;
                bhf[nt][0] = *reinterpret_cast<const uint32_t*>(ph);
                bhf[nt][1] = *reinterpret_cast<const uint32_t*>(ph + 16);
                blf[nt][0] = *reinterpret_cast<const uint32_t*>(pl);
                blf[nt][1] = *reinterpret_cast<const uint32_t*>(pl + 16);
            }
#pragma unroll
            for (int mt = 0; mt < 4; ++mt) {
                int r = wm * 64 + mt * 16 + g;
                const char* ph = Ah + r * P1_ROWB + kb;
                const char* pl = Al + r * P1_ROWB + kb;
                uint32_t ahf[4], alf[4];
                ahf[0] = *reinterpret_cast<const uint32_t*>(ph);
                ahf[1] = *reinterpret_cast<const uint32_t*>(ph + 8 * P1_ROWB);
                ahf[2] = *reinterpret_cast<const uint32_t*>(ph + 16);
                ahf[3] = *reinterpret_cast<const uint32_t*>(ph + 8 * P1_ROWB + 16);
                alf[0] = *reinterpret_cast<const uint32_t*>(pl);
                alf[1] = *reinterpret_cast<const uint32_t*>(pl + 8 * P1_ROWB);
                alf[2] = *reinterpret_cast<const uint32_t*>(pl + 16);
                alf[3] = *reinterpret_cast<const uint32_t*>(pl + 8 * P1_ROWB + 16);
#pragma unroll
                for (int nt = 0; nt < 4; ++nt) {
                    mma_bf16(acc[mt][nt], ahf, bhf[nt]);
                    mma_bf16(acc[mt][nt], ahf, blf[nt]);
                    mma_bf16(acc[mt][nt], alf, bhf[nt]);
                }
            }
        }
        __syncthreads();
    }

    // ---- epilogue: stage [tloc][n][b] in SMEM, then coalesced STG ----
    float* stage = reinterpret_cast<float*>(sm);
#pragma unroll
    for (int mt = 0; mt < 4; ++mt) {
        int lm0 = wm * 64 + mt * 16 + g;
        int lm1 = lm0 + 8;
        int tl0 = lm0 >> 5, bb0 = lm0 & 31;
        int tl1 = lm1 >> 5, bb1 = lm1 & 31;
#pragma unroll
        for (int nt = 0; nt < 4; ++nt) {
            int nl = wn * 32 + nt * 8 + 2 * t4;
            float bv0 = bias_sm[nl], bv1 = bias_sm[nl + 1];
            stage[(tl0 * 128 + nl) * EPI_STRIDE + bb0]       = acc[mt][nt][0] + bv0;
            stage[(tl0 * 128 + nl + 1) * EPI_STRIDE + bb0]   = acc[mt][nt][1] + bv1;
            stage[(tl1 * 128 + nl) * EPI_STRIDE + bb1]       = acc[mt][nt][2] + bv0;
            stage[(tl1 * 128 + nl + 1) * EPI_STRIDE + bb1]   = acc[mt][nt][3] + bv1;
        }
    }
    __syncthreads();

    const size_t tbase = (size_t)(gm0 >> 5);
#pragma unroll
    for (int it = 0; it < 16; ++it) {
        int i = tid + it * 256;
        int row = i >> 3;
        int q = i & 7;
        int tloc = row >> 7, n = row & 127;
        float4 val = *reinterpret_cast<const float4*>(&stage[row * EPI_STRIDE + q * 4]);
        float* dst = g_gx + ((tbase + tloc) * GG + gn0 + n) * 32 + q * 4;
        *reinterpret_cast<float4*>(dst) = val;
    }
}

// ============================================================================
// Phase 2: persistent scan; warp-0 acquire poll, per-warp slices, 3 bars/step
// ============================================================================
#define HW_SLAB 9216                          // per-warp: 2 ver * 32 b * 144B
#define VER_STR 4608                          // 32 b * 144B
#define OFF_PART (8 * HW_SLAB)                // 73728
#define PART_SLABW (32 * 36)
#define OFF_HROW (OFF_PART + 8 * PART_SLABW * 4)   // 110592
#define SCAN_SMEM (OFF_HROW + 32 * 9 * 4 + 64)     // 111808

__global__ __launch_bounds__(256, 1) void lstm_scan_tc(
    const float* __restrict__ Wh,
    float* __restrict__ y, float* __restrict__ hfin, float* __restrict__ cfin)
{
    extern __shared__ char sm[];
    const int tid = threadIdx.x;
    const int wid = tid >> 5;
    const int lane = tid & 31;
    const int g = lane >> 2;
    const int t4 = lane & 3;
    const int J0 = blockIdx.x * 8;
    const int kb = wid * 64;

    // ---- preload Wh A-fragments into registers (once) ----
    uint32_t ahf[2][4][4], alf[2][4][4];
#pragma unroll
    for (int mt = 0; mt < 2; ++mt) {
        int r0 = mt * 16 + g, r1 = r0 + 8;
        int grow0 = (r0 >> 3) * 512 + J0 + (r0 & 7);
        int grow1 = (r1 >> 3) * 512 + J0 + (r1 & 7);
#pragma unroll
        for (int ks = 0; ks < 4; ++ks) {
            int k0 = kb + ks * 16 + 2 * t4;
            float2 w00 = *reinterpret_cast<const float2*>(&Wh[(size_t)grow0 * HH + k0]);
            float2 w10 = *reinterpret_cast<const float2*>(&Wh[(size_t)grow1 * HH + k0]);
            float2 w01 = *reinterpret_cast<const float2*>(&Wh[(size_t)grow0 * HH + k0 + 8]);
            float2 w11 = *reinterpret_cast<const float2*>(&Wh[(size_t)grow1 * HH + k0 + 8]);
            split_pair(w00.x, w00.y, ahf[mt][ks][0], alf[mt][ks][0]);
            split_pair(w10.x, w10.y, ahf[mt][ks][1], alf[mt][ks][1]);
            split_pair(w01.x, w01.y, ahf[mt][ks][2], alf[mt][ks][2]);
            split_pair(w11.x, w11.y, ahf[mt][ks][3], alf[mt][ks][3]);
        }
    }

    char* wslab = sm + wid * HW_SLAB;
    const int jj = tid >> 5;
    const int b = tid & 31;

    float c_reg = 0.0f, h_last = 0.0f;

    for (int t = 0; t < TT; ++t) {
        const int p = t & 1;

        // gx prefetch (coalesced; independent of h, issued before the wait)
        const float* gxp = g_gx + ((size_t)t * GG + J0 + jj) * 32 + b;
        float gx0 = gxp[0];
        float gx1 = gxp[512 * 32];
        float gx2 = gxp[1024 * 32];
        float gx3 = gxp[1536 * 32];

        // ---- warp 0 polls all 64 flags (acquire + backoff); bar broadcasts ----
        if (t > 0) {
            if (wid == 0) {
                for (;;) {
                    int f0 = ldflag_acq(&g_flags[lane]);
                    int f1 = ldflag_acq(&g_flags[lane + 32]);
                    if (__all_sync(0xFFFFFFFFu, (f0 >= t) && (f1 >= t))) break;
                    __nanosleep(32);
                }
            }
            __syncthreads();
        }

        // ---- per-warp h slice copy (L2 .cg): k-chunk [kb,kb+64), hi+lo ----
        const uint4* __restrict__ src = &g_hb[p][0][0];   // [ver*2048 + b*64 + kq]
#pragma unroll
        for (int it = 0; it < 16; ++it) {
            int idx = lane + it * 32;          // 0..511
            int ver = idx >> 8;
            int rem = idx & 255;
            int bb = rem >> 3, j = rem & 7;
            uint4 val = __ldcg(&src[ver * 2048 + bb * 64 + wid * 8 + j]);
            *reinterpret_cast<uint4*>(wslab + ver * VER_STR + bb * 144 + j * 16) = val;
        }
        __syncwarp();

        // ---- MMA: 32 gate rows x 32 batches over warp k-chunk, bf16x3 ----
        float acc[2][4][4];
#pragma unroll
        for (int a = 0; a < 2; ++a)
#pragma unroll
            for (int c2 = 0; c2 < 4; ++c2)
#pragma unroll
                for (int c = 0; c < 4; ++c) acc[a][c2][c] = 0.0f;

#pragma unroll
        for (int ks = 0; ks < 4; ++ks) {
            uint32_t bhf[4][2], blf[4][2];
#pragma unroll
            for (int nt = 0; nt < 4; ++nt) {
                const char* ph = wslab + (nt * 8 + g) * 144 + (ks * 8 + t4) * 4;
                bhf[nt][0] = *reinterpret_cast<const uint32_t*>(ph);
                bhf[nt][1] = *reinterpret_cast<const uint32_t*>(ph + 16);
                blf[nt][0] = *reinterpret_cast<const uint32_t*>(ph + VER_STR);
                blf[nt][1] = *reinterpret_cast<const uint32_t*>(ph + VER_STR + 16);
            }
#pragma unroll
            for (int mt = 0; mt < 2; ++mt) {
#pragma unroll
                for (int nt = 0; nt < 4; ++nt) {
                    mma_bf16(acc[mt][nt], ahf[mt][ks], bhf[nt]);
                    mma_bf16(acc[mt][nt], ahf[mt][ks], blf[nt]);
                    mma_bf16(acc[mt][nt], alf[mt][ks], bhf[nt]);
                }
            }
        }

        // ---- partials to SMEM ----
        {
            float* slab = reinterpret_cast<float*>(sm + OFF_PART) + wid * PART_SLABW;
#pragma unroll
            for (int mt = 0; mt < 2; ++mt) {
                int m = mt * 16 + g;
#pragma unroll
                for (int nt = 0; nt < 4; ++nt) {
                    int n = nt * 8 + 2 * t4;
                    *reinterpret_cast<float2*>(&slab[m * 36 + n]) =
                        make_float2(acc[mt][nt][0], acc[mt][nt][1]);
                    *reinterpret_cast<float2*>(&slab[(m + 8) * 36 + n]) =
                        make_float2(acc[mt][nt][2], acc[mt][nt][3]);
                }
            }
        }
        __syncthreads();

        // ---- fused reduce + gate math: thread (jj, b) ----
        {
            const float* pbase = reinterpret_cast<const float*>(sm + OFF_PART);
            float gate[4] = {gx0, gx1, gx2, gx3};
#pragma unroll
            for (int q = 0; q < 4; ++q) {
                const int m = q * 8 + jj;
#pragma unroll
                for (int w = 0; w < 8; ++w)
                    gate[q] += pbase[w * PART_SLABW + m * 36 + b];
            }
            float cn = sigf(gate[1]) * c_reg + sigf(gate[0]) * tanh_fast(gate[2]);
            float hn = sigf(gate[3]) * tanh_fast(cn);
            c_reg = cn;
            h_last = hn;
            reinterpret_cast<float*>(sm + OFF_HROW)[b * 9 + jj] = hn;
        }
        __syncthreads();

        // ---- writer warp 0: pack h -> global hi/lo + y; fence; publish ----
        if (tid < 32) {
            const float* hr = reinterpret_cast<const float*>(sm + OFF_HROW) + tid * 9;
            float h0 = hr[0], h1 = hr[1], h2 = hr[2], h3 = hr[3];
            float h4 = hr[4], h5 = hr[5], h6 = hr[6], h7 = hr[7];
            uint32_t hi01, lo01, hi23, lo23, hi45, lo45, hi67, lo67;
            split_pair(h0, h1, hi01, lo01);
            split_pair(h2, h3, hi23, lo23);
            split_pair(h4, h5, hi45, lo45);
            split_pair(h6, h7, hi67, lo67);
            int ci = tid * 64 + (J0 >> 3);
            g_hb[p ^ 1][0][ci] = make_uint4(hi01, hi23, hi45, hi67);
            g_hb[p ^ 1][1][ci] = make_uint4(lo01, lo23, lo45, lo67);
            float* yp = y + ((size_t)tid * TT + t) * HH + J0;
            *reinterpret_cast<float4*>(yp)     = make_float4(h0, h1, h2, h3);
            *reinterpret_cast<float4*>(yp + 4) = make_float4(h4, h5, h6, h7);
            __syncwarp();
            if (tid == 0 && t < TT - 1) {
                __threadfence();                  // drain h stores to L2
                g_flags[blockIdx.x] = t + 1;      // publish
            }
        }
    }

    hfin[(size_t)b * HH + J0 + jj] = h_last;
    cfin[(size_t)b * HH + J0 + jj] = c_reg;
}

// ============================================================================
// launch (2 kernels; init folded into gemm)
// ============================================================================
extern "C" void kernel_launch(void* const* d_in, const int* in_sizes, int n_in,
                              void* d_out, int out_size) {
    const float* x  = (const float*)d_in[0];
    const float* Wi = (const float*)d_in[1];
    const float* bi = (const float*)d_in[2];
    const float* Wh = (const float*)d_in[3];
    const float* bh = (const float*)d_in[4];

    float* y    = (float*)d_out;
    float* hfin = y + (size_t)BB * TT * HH;
    float* cfin = hfin + (size_t)BB * HH;

    cudaFuncSetAttribute(gemm_gx_tc,
                         cudaFuncAttributeMaxDynamicSharedMemorySize, P1_SMEM);
    cudaFuncSetAttribute(lstm_scan_tc,
                         cudaFuncAttributeMaxDynamicSharedMemorySize, SCAN_SMEM);

    gemm_gx_tc<<<dim3(16, 512), 256, P1_SMEM>>>(x, Wi, bi, bh);
    lstm_scan_tc<<<NCTA2, 256, SCAN_SMEM>>>(Wh, y, hfin, cfin);
}

// round 9
// speedup vs baseline: 1.9061x; 1.1917x over previous
#include <cuda_runtime.h>
#include <cuda_bf16.h>
#include <cstdint>

// ============================================================================
// CustomLSTM: B=32, T=2048, I=512, H=512 (4H=2048)
// Phase 1: gx = x@Wi^T + bi + bh  -- bf16x3 HMMA, 128x128 tiles, SMEM-staged
//          transposed epilogue -> gx[t][g][b]. Init folded into block (0,0).
// Phase 2: persistent scan, 128 CTAs x 4 hidden units. Warp 0 polls padded
//          flags (1 per 128B line, acquire, NO backoff); per-warp h slice
//          copy via .cg; y stores after publish; Wh A-frags in registers.
// NOTE: harness PTX target is compute_103 (no 'a') -> tcgen05 unavailable.
// ============================================================================

#define TT 2048
#define BB 32
#define II 512
#define HH 512
#define GG 2048

#define NCTA2 128

// ---------------- device scratch ----------------
__device__ float g_gx[(size_t)TT * GG * BB];     // [t][g][b]  512 MB
__device__ uint4 g_hb[2][2][2048];               // ping x {hi,lo} x (b*64+kq)
__device__ int   g_flags[NCTA2 * 32];            // one flag per 128B line

__device__ __forceinline__ float sigf(float x) { return 1.0f / (1.0f + __expf(-x)); }
__device__ __forceinline__ float tanh_fast(float x) {
    float r;
    asm("tanh.approx.f32 %0, %1;" : "=f"(r) : "f"(x));
    return r;
}
__device__ __forceinline__ int ldflag_acq(const int* p) {
    int v;
    asm volatile("ld.acquire.gpu.global.b32 %0, [%1];" : "=r"(v) : "l"(p) : "memory");
    return v;
}

// pack two floats' bf16 parts; hi2 = {bf16(f1)|bf16(f0)}, lo2 = residuals
__device__ __forceinline__ void split_pair(float f0, float f1, uint32_t& hi2, uint32_t& lo2) {
    uint32_t h;
    asm("cvt.rn.bf16x2.f32 %0, %1, %2;" : "=r"(h) : "f"(f1), "f"(f0));
    float h0 = __uint_as_float(h << 16);
    float h1 = __uint_as_float(h & 0xFFFF0000u);
    asm("cvt.rn.bf16x2.f32 %0, %1, %2;" : "=r"(lo2) : "f"(f1 - h1), "f"(f0 - h0));
    hi2 = h;
}

__device__ __forceinline__ void mma_bf16(float* d, const uint32_t* a, const uint32_t* b) {
    asm volatile(
        "mma.sync.aligned.m16n8k16.row.col.f32.bf16.bf16.f32 "
        "{%0,%1,%2,%3}, {%4,%5,%6,%7}, {%8,%9}, {%0,%1,%2,%3};"
        : "+f"(d[0]), "+f"(d[1]), "+f"(d[2]), "+f"(d[3])
        : "r"(a[0]), "r"(a[1]), "r"(a[2]), "r"(a[3]), "r"(b[0]), "r"(b[1]));
}

// ============================================================================
// Phase 1: bf16x3 HMMA GEMM; SMEM-staged transposed epilogue; init fold
// ============================================================================
#define P1_ROWB 80
#define P1_OPB  (128 * P1_ROWB)
#define P1_BUFB (4 * P1_OPB)
#define P1_SMEM (2 * P1_BUFB + 512)
#define EPI_STRIDE 36

__global__ __launch_bounds__(256, 2) void gemm_gx_tc(
    const float* __restrict__ x, const float* __restrict__ Wi,
    const float* __restrict__ bi, const float* __restrict__ bh)
{
    extern __shared__ char sm[];
    float* bias_sm = reinterpret_cast<float*>(sm + 2 * P1_BUFB);

    const int tid = threadIdx.x;
    const int wid = tid >> 5;
    const int lane = tid & 31;
    const int g = lane >> 2;
    const int t4 = lane & 3;
    const int wm = wid >> 2;
    const int wn = wid & 3;

    const int gn0 = blockIdx.x * 128;
    const int gm0 = blockIdx.y * 128;

    // ---- folded init (block 0,0): zero h ping 0 and padded flags ----
    if (blockIdx.x == 0 && blockIdx.y == 0) {
#pragma unroll
        for (int it = 0; it < 16; ++it) {
            int i = tid + it * 256;
            g_hb[0][i >> 11][i & 2047] = make_uint4(0u, 0u, 0u, 0u);
        }
#pragma unroll
        for (int it = 0; it < 16; ++it)
            g_flags[tid + it * 256] = 0;
    }

    if (tid < 128) bias_sm[tid] = bi[gn0 + tid] + bh[gn0 + tid];

    const float* asrc[4];
    const float* bsrc[4];
    uint32_t adst[4], bdst[4];
#pragma unroll
    for (int it = 0; it < 4; ++it) {
        int aidx = tid + it * 256;
        int row = aidx >> 3, q = aidx & 7;
        int m = gm0 + row;
        asrc[it] = x + ((size_t)(m & 31) * TT + (m >> 5)) * II + q * 4;
        adst[it] = row * P1_ROWB + q * 8;
        bsrc[it] = Wi + (size_t)(gn0 + row) * II + q * 4;
        bdst[it] = row * P1_ROWB + q * 8;
    }

    float acc[4][4][4];
#pragma unroll
    for (int a = 0; a < 4; ++a)
#pragma unroll
        for (int b = 0; b < 4; ++b)
#pragma unroll
            for (int c = 0; c < 4; ++c) acc[a][b][c] = 0.0f;

    float4 v[8];
#pragma unroll
    for (int it = 0; it < 4; ++it) {
        v[it]     = *reinterpret_cast<const float4*>(asrc[it]);
        v[4 + it] = *reinterpret_cast<const float4*>(bsrc[it]);
    }

    for (int kt = 0; kt < 16; ++kt) {
        char* buf = sm + (kt & 1) * P1_BUFB;
#pragma unroll
        for (int it = 0; it < 8; ++it) {
            float4 w = v[it];
            uint32_t h01, l01, h23, l23;
            split_pair(w.x, w.y, h01, l01);
            split_pair(w.z, w.w, h23, l23);
            char* dhi = buf + ((it < 4) ? adst[it] : (2 * P1_OPB + bdst[it - 4]));
            *reinterpret_cast<uint2*>(dhi) = make_uint2(h01, h23);
            *reinterpret_cast<uint2*>(dhi + P1_OPB) = make_uint2(l01, l23);
        }
        __syncthreads();

        if (kt < 15) {
            int ko = (kt + 1) * 32;
#pragma unroll
            for (int it = 0; it < 4; ++it) {
                v[it]     = *reinterpret_cast<const float4*>(asrc[it] + ko);
                v[4 + it] = *reinterpret_cast<const float4*>(bsrc[it] + ko);
            }
        }

        const char* Ah = buf;
        const char* Al = buf + P1_OPB;
        const char* Bh = buf + 2 * P1_OPB;
        const char* Bl = buf + 3 * P1_OPB;

#pragma unroll
        for (int ks = 0; ks < 2; ++ks) {
            const int kb = ks * 32 + 4 * t4;
            uint32_t bhf[4][2], blf[4][2];
#pragma unroll
            for (int nt = 0; nt < 4; ++nt) {
                int n = wn * 32 + nt * 8 + g;
                const char* ph = Bh + n * P1_ROWB + kb;
                const char* pl = Bl + n * P1_ROWB + kb;
                bhf[nt][0] = *reinterpret_cast<const uint32_t*>(ph);
                bhf[nt][1] = *reinterpret_cast<const uint32_t*>(ph + 16);
                blf[nt][0] = *reinterpret_cast<const uint32_t*>(pl);
                blf[nt][1] = *reinterpret_cast<const uint32_t*>(pl + 16);
            }
#pragma unroll
            for (int mt = 0; mt < 4; ++mt) {
                int r = wm * 64 + mt * 16 + g;
                const char* ph = Ah + r * P1_ROWB + kb;
                const char* pl = Al + r * P1_ROWB + kb;
                uint32_t ahf[4], alf[4];
                ahf[0] = *reinterpret_cast<const uint32_t*>(ph);
                ahf[1] = *reinterpret_cast<const uint32_t*>(ph + 8 * P1_ROWB);
                ahf[2] = *reinterpret_cast<const uint32_t*>(ph + 16);
                ahf[3] = *reinterpret_cast<const uint32_t*>(ph + 8 * P1_ROWB + 16);
                alf[0] = *reinterpret_cast<const uint32_t*>(pl);
                alf[1] = *reinterpret_cast<const uint32_t*>(pl + 8 * P1_ROWB);
                alf[2] = *reinterpret_cast<const uint32_t*>(pl + 16);
                alf[3] = *reinterpret_cast<const uint32_t*>(pl + 8 * P1_ROWB + 16);
#pragma unroll
                for (int nt = 0; nt < 4; ++nt) {
                    mma_bf16(acc[mt][nt], ahf, bhf[nt]);
                    mma_bf16(acc[mt][nt], ahf, blf[nt]);
                    mma_bf16(acc[mt][nt], alf, bhf[nt]);
                }
            }
        }
        __syncthreads();
    }

    // ---- epilogue: stage [tloc][n][b] in SMEM, then coalesced STG ----
    float* stage = reinterpret_cast<float*>(sm);
#pragma unroll
    for (int mt = 0; mt < 4; ++mt) {
        int lm0 = wm * 64 + mt * 16 + g;
        int lm1 = lm0 + 8;
        int tl0 = lm0 >> 5, bb0 = lm0 & 31;
        int tl1 = lm1 >> 5, bb1 = lm1 & 31;
#pragma unroll
        for (int nt = 0; nt < 4; ++nt) {
            int nl = wn * 32 + nt * 8 + 2 * t4;
            float bv0 = bias_sm[nl], bv1 = bias_sm[nl + 1];
            stage[(tl0 * 128 + nl) * EPI_STRIDE + bb0]       = acc[mt][nt][0] + bv0;
            stage[(tl0 * 128 + nl + 1) * EPI_STRIDE + bb0]   = acc[mt][nt][1] + bv1;
            stage[(tl1 * 128 + nl) * EPI_STRIDE + bb1]       = acc[mt][nt][2] + bv0;
            stage[(tl1 * 128 + nl + 1) * EPI_STRIDE + bb1]   = acc[mt][nt][3] + bv1;
        }
    }
    __syncthreads();

    const size_t tbase = (size_t)(gm0 >> 5);
#pragma unroll
    for (int it = 0; it < 16; ++it) {
        int i = tid + it * 256;
        int row = i >> 3;
        int q = i & 7;
        int tloc = row >> 7, n = row & 127;
        float4 val = *reinterpret_cast<const float4*>(&stage[row * EPI_STRIDE + q * 4]);
        float* dst = g_gx + ((tbase + tloc) * GG + gn0 + n) * 32 + q * 4;
        *reinterpret_cast<float4*>(dst) = val;
    }
}

// ============================================================================
// Phase 2: persistent scan. 128 CTAs x 4 hidden units (16 gate rows).
// ============================================================================
#define HW_SLAB 9216                          // per-warp: 2 ver * 32 b * 144B
#define VER_STR 4608                          // 32 b * 144B
#define OFF_PART (8 * HW_SLAB)                // 73728
#define PART_SLABW (16 * 36)                  // 576 floats per warp slab
#define OFF_HROW (OFF_PART + 8 * PART_SLABW * 4)   // 92160
#define SCAN_SMEM (OFF_HROW + 32 * 5 * 4 + 64)     // 92864

__global__ __launch_bounds__(256, 1) void lstm_scan_tc(
    const float* __restrict__ Wh,
    float* __restrict__ y, float* __restrict__ hfin, float* __restrict__ cfin)
{
    extern __shared__ char sm[];
    const int tid = threadIdx.x;
    const int wid = tid >> 5;
    const int lane = tid & 31;
    const int g = lane >> 2;
    const int t4 = lane & 3;
    const int J0 = blockIdx.x * 4;
    const int kb = wid * 64;

    // ---- preload Wh A-fragments into registers (once) ----
    // m16 tile rows: r0 = g (gate q=g>>2, unit jj=g&3), r1 = g+8 (q+2, jj)
    uint32_t ahf[4][4], alf[4][4];
    {
        const int grow0 = (g >> 2) * 512 + J0 + (g & 3);
        const int grow1 = grow0 + 1024;
#pragma unroll
        for (int ks = 0; ks < 4; ++ks) {
            int k0 = kb + ks * 16 + 2 * t4;
            float2 w00 = *reinterpret_cast<const float2*>(&Wh[(size_t)grow0 * HH + k0]);
            float2 w10 = *reinterpret_cast<const float2*>(&Wh[(size_t)grow1 * HH + k0]);
            float2 w01 = *reinterpret_cast<const float2*>(&Wh[(size_t)grow0 * HH + k0 + 8]);
            float2 w11 = *reinterpret_cast<const float2*>(&Wh[(size_t)grow1 * HH + k0 + 8]);
            split_pair(w00.x, w00.y, ahf[ks][0], alf[ks][0]);
            split_pair(w10.x, w10.y, ahf[ks][1], alf[ks][1]);
            split_pair(w01.x, w01.y, ahf[ks][2], alf[ks][2]);
            split_pair(w11.x, w11.y, ahf[ks][3], alf[ks][3]);
        }
    }

    char* wslab = sm + wid * HW_SLAB;
    const int jj = tid >> 5;                 // valid for tid<128 (0..3)
    const int b = tid & 31;

    float c_reg = 0.0f, h_last = 0.0f;

    for (int t = 0; t < TT; ++t) {
        const int p = t & 1;

        // gx prefetch (coalesced; in flight during the wait)
        const float* gxp = g_gx + ((size_t)t * GG + J0 + jj) * 32 + b;
        float gx0 = 0.f, gx1 = 0.f, gx2 = 0.f, gx3 = 0.f;
        if (tid < 128) {
            gx0 = gxp[0];
            gx1 = gxp[512 * 32];
            gx2 = gxp[1024 * 32];
            gx3 = gxp[1536 * 32];
        }

        // ---- warp 0 polls 128 padded flags (acquire, no backoff) ----
        if (t > 0) {
            if (wid == 0) {
                for (;;) {
                    int f0 = ldflag_acq(&g_flags[lane * 32]);
                    int f1 = ldflag_acq(&g_flags[(lane + 32) * 32]);
                    int f2 = ldflag_acq(&g_flags[(lane + 64) * 32]);
                    int f3 = ldflag_acq(&g_flags[(lane + 96) * 32]);
                    if (__all_sync(0xFFFFFFFFu,
                                   (f0 >= t) && (f1 >= t) && (f2 >= t) && (f3 >= t)))
                        break;
                }
            }
            __syncthreads();
        }

        // ---- per-warp h slice copy (L2 .cg): k-chunk [kb,kb+64), hi+lo ----
        const uint4* __restrict__ src = &g_hb[p][0][0];   // [ver*2048 + b*64 + kq]
#pragma unroll
        for (int it = 0; it < 16; ++it) {
            int idx = lane + it * 32;          // 0..511
            int ver = idx >> 8;
            int rem = idx & 255;
            int bb = rem >> 3, j = rem & 7;
            uint4 val = __ldcg(&src[ver * 2048 + bb * 64 + wid * 8 + j]);
            *reinterpret_cast<uint4*>(wslab + ver * VER_STR + bb * 144 + j * 16) = val;
        }
        __syncwarp();

        // ---- MMA: 16 gate rows x 32 batches over warp k-chunk, bf16x3 ----
        float acc[4][4];
#pragma unroll
        for (int nt = 0; nt < 4; ++nt)
#pragma unroll
            for (int c = 0; c < 4; ++c) acc[nt][c] = 0.0f;

#pragma unroll
        for (int ks = 0; ks < 4; ++ks) {
            uint32_t bhf[4][2], blf[4][2];
#pragma unroll
            for (int nt = 0; nt < 4; ++nt) {
                const char* ph = wslab + (nt * 8 + g) * 144 + (ks * 8 + t4) * 4;
                bhf[nt][0] = *reinterpret_cast<const uint32_t*>(ph);
                bhf[nt][1] = *reinterpret_cast<const uint32_t*>(ph + 16);
                blf[nt][0] = *reinterpret_cast<const uint32_t*>(ph + VER_STR);
                blf[nt][1] = *reinterpret_cast<const uint32_t*>(ph + VER_STR + 16);
            }
#pragma unroll
            for (int nt = 0; nt < 4; ++nt) {
                mma_bf16(acc[nt], ahf[ks], bhf[nt]);
                mma_bf16(acc[nt], ahf[ks], blf[nt]);
                mma_bf16(acc[nt], alf[ks], bhf[nt]);
            }
        }

        // ---- partials to SMEM ----
        {
            float* slab = reinterpret_cast<float*>(sm + OFF_PART) + wid * PART_SLABW;
#pragma unroll
            for (int nt = 0; nt < 4; ++nt) {
                int n = nt * 8 + 2 * t4;
                *reinterpret_cast<float2*>(&slab[g * 36 + n]) =
                    make_float2(acc[nt][0], acc[nt][1]);
                *reinterpret_cast<float2*>(&slab[(g + 8) * 36 + n]) =
                    make_float2(acc[nt][2], acc[nt][3]);
            }
        }
        __syncthreads();

        // ---- fused reduce + gate math: thread (jj, b), tid<128 ----
        if (tid < 128) {
            const float* pbase = reinterpret_cast<const float*>(sm + OFF_PART);
            float gate[4] = {gx0, gx1, gx2, gx3};
#pragma unroll
            for (int q = 0; q < 4; ++q) {
                const int m = q * 4 + jj;
#pragma unroll
                for (int w = 0; w < 8; ++w)
                    gate[q] += pbase[w * PART_SLABW + m * 36 + b];
            }
            float cn = sigf(gate[1]) * c_reg + sigf(gate[0]) * tanh_fast(gate[2]);
            float hn = sigf(gate[3]) * tanh_fast(cn);
            c_reg = cn;
            h_last = hn;
            reinterpret_cast<float*>(sm + OFF_HROW)[b * 5 + jj] = hn;
        }
        __syncthreads();

        // ---- writer warp 0: h -> global hi/lo; fence; publish; THEN y ----
        if (tid < 32) {
            const float* hr = reinterpret_cast<const float*>(sm + OFF_HROW) + tid * 5;
            float h0 = hr[0], h1 = hr[1], h2 = hr[2], h3 = hr[3];
            uint32_t hi01, lo01, hi23, lo23;
            split_pair(h0, h1, hi01, lo01);
            split_pair(h2, h3, hi23, lo23);
            uint32_t* hb32 = reinterpret_cast<uint32_t*>(&g_hb[p ^ 1][0][0]);
            int u32i = tid * 256 + (J0 >> 1);
            *reinterpret_cast<uint2*>(hb32 + u32i)        = make_uint2(hi01, hi23);
            *reinterpret_cast<uint2*>(hb32 + 8192 + u32i) = make_uint2(lo01, lo23);
            __syncwarp();
            if (tid == 0 && t < TT - 1) {
                __threadfence();                      // drain h stores to L2
                g_flags[blockIdx.x * 32] = t + 1;     // publish
            }
            // y after publish (not consumer-visible, off the critical path)
            float* yp = y + ((size_t)tid * TT + t) * HH + J0;
            *reinterpret_cast<float4*>(yp) = make_float4(h0, h1, h2, h3);
        }
    }

    if (tid < 128) {
        hfin[(size_t)b * HH + J0 + jj] = h_last;
        cfin[(size_t)b * HH + J0 + jj] = c_reg;
    }
}

// ============================================================================
// launch (2 kernels; init folded into gemm)
// ============================================================================
extern "C" void kernel_launch(void* const* d_in, const int* in_sizes, int n_in,
                              void* d_out, int out_size) {
    const float* x  = (const float*)d_in[0];
    const float* Wi = (const float*)d_in[1];
    const float* bi = (const float*)d_in[2];
    const float* Wh = (const float*)d_in[3];
    const float* bh = (const float*)d_in[4];

    float* y    = (float*)d_out;
    float* hfin = y + (size_t)BB * TT * HH;
    float* cfin = hfin + (size_t)BB * HH;

    cudaFuncSetAttribute(gemm_gx_tc,
                         cudaFuncAttributeMaxDynamicSharedMemorySize, P1_SMEM);
    cudaFuncSetAttribute(lstm_scan_tc,
                         cudaFuncAttributeMaxDynamicSharedMemorySize, SCAN_SMEM);

    gemm_gx_tc<<<dim3(16, 512), 256, P1_SMEM>>>(x, Wi, bi, bh);
    lstm_scan_tc<<<NCTA2, 256, SCAN_SMEM>>>(Wh, y, hfin, cfin);
}

// round 10
// speedup vs baseline: 2.0836x; 1.0931x over previous
#include <cuda_runtime.h>
#include <cuda_bf16.h>
#include <cuda_fp16.h>
#include <cstdint>

// ============================================================================
// CustomLSTM: B=32, T=2048, I=512, H=512 (4H=2048)
// Phase 1: gx = x@Wi^T + bi + bh  -- bf16x3 HMMA, 128x128 tiles, SMEM-staged
//          transposed epilogue -> gx[t][g][b]. Init folded into block (0,0).
// Phase 2: persistent scan, 128 CTAs x 4 hidden units, fp16x2 HMMA:
//          Wh as fp16 hi+lo (registers), h exchanged as SINGLE fp16 (32KB,
//          halves L2 broadcast), 2 MMAs per tile instead of 3.
//          Warp-0 padded-flag acquire poll (R9-proven sync structure).
// NOTE: harness PTX target is compute_103 (no 'a') -> tcgen05 unavailable.
// ============================================================================

#define TT 2048
#define BB 32
#define II 512
#define HH 512
#define GG 2048

#define NCTA2 128

// ---------------- device scratch ----------------
__device__ float g_gx[(size_t)TT * GG * BB];     // [t][g][b]  512 MB
__device__ uint2 g_hf[2][BB * 128];              // ping x [b][j/4] fp16 h (32KB)
__device__ int   g_flags[NCTA2 * 32];            // one flag per 128B line

__device__ __forceinline__ float sigf(float x) { return 1.0f / (1.0f + __expf(-x)); }
__device__ __forceinline__ float tanh_fast(float x) {
    float r;
    asm("tanh.approx.f32 %0, %1;" : "=f"(r) : "f"(x));
    return r;
}
__device__ __forceinline__ int ldflag_acq(const int* p) {
    int v;
    asm volatile("ld.acquire.gpu.global.b32 %0, [%1];" : "=r"(v) : "l"(p) : "memory");
    return v;
}

// ---- bf16 split (phase 1) ----
__device__ __forceinline__ void split_pair(float f0, float f1, uint32_t& hi2, uint32_t& lo2) {
    uint32_t h;
    asm("cvt.rn.bf16x2.f32 %0, %1, %2;" : "=r"(h) : "f"(f1), "f"(f0));
    float h0 = __uint_as_float(h << 16);
    float h1 = __uint_as_float(h & 0xFFFF0000u);
    asm("cvt.rn.bf16x2.f32 %0, %1, %2;" : "=r"(lo2) : "f"(f1 - h1), "f"(f0 - h0));
    hi2 = h;
}

// ---- fp16 split (scan Wh) ----
__device__ __forceinline__ void split_pair_f16(float f0, float f1, uint32_t& hi2, uint32_t& lo2) {
    uint32_t h;
    asm("cvt.rn.f16x2.f32 %0, %1, %2;" : "=r"(h) : "f"(f1), "f"(f0));
    __half2 hh = *reinterpret_cast<__half2*>(&h);
    float h0 = __low2float(hh), h1 = __high2float(hh);
    asm("cvt.rn.f16x2.f32 %0, %1, %2;" : "=r"(lo2) : "f"(f1 - h1), "f"(f0 - h0));
    hi2 = h;
}
__device__ __forceinline__ uint32_t pack_f16(float f0, float f1) {
    uint32_t h;
    asm("cvt.rn.f16x2.f32 %0, %1, %2;" : "=r"(h) : "f"(f1), "f"(f0));
    return h;
}

__device__ __forceinline__ void mma_bf16(float* d, const uint32_t* a, const uint32_t* b) {
    asm volatile(
        "mma.sync.aligned.m16n8k16.row.col.f32.bf16.bf16.f32 "
        "{%0,%1,%2,%3}, {%4,%5,%6,%7}, {%8,%9}, {%0,%1,%2,%3};"
        : "+f"(d[0]), "+f"(d[1]), "+f"(d[2]), "+f"(d[3])
        : "r"(a[0]), "r"(a[1]), "r"(a[2]), "r"(a[3]), "r"(b[0]), "r"(b[1]));
}
__device__ __forceinline__ void mma_f16(float* d, const uint32_t* a, const uint32_t* b) {
    asm volatile(
        "mma.sync.aligned.m16n8k16.row.col.f32.f16.f16.f32 "
        "{%0,%1,%2,%3}, {%4,%5,%6,%7}, {%8,%9}, {%0,%1,%2,%3};"
        : "+f"(d[0]), "+f"(d[1]), "+f"(d[2]), "+f"(d[3])
        : "r"(a[0]), "r"(a[1]), "r"(a[2]), "r"(a[3]), "r"(b[0]), "r"(b[1]));
}

// ============================================================================
// Phase 1: bf16x3 HMMA GEMM; SMEM-staged transposed epilogue; init fold
// ============================================================================
#define P1_ROWB 80
#define P1_OPB  (128 * P1_ROWB)
#define P1_BUFB (4 * P1_OPB)
#define P1_SMEM (2 * P1_BUFB + 512)
#define EPI_STRIDE 36

__global__ __launch_bounds__(256, 2) void gemm_gx_tc(
    const float* __restrict__ x, const float* __restrict__ Wi,
    const float* __restrict__ bi, const float* __restrict__ bh)
{
    extern __shared__ char sm[];
    float* bias_sm = reinterpret_cast<float*>(sm + 2 * P1_BUFB);

    const int tid = threadIdx.x;
    const int wid = tid >> 5;
    const int lane = tid & 31;
    const int g = lane >> 2;
    const int t4 = lane & 3;
    const int wm = wid >> 2;
    const int wn = wid & 3;

    const int gn0 = blockIdx.x * 128;
    const int gm0 = blockIdx.y * 128;

    // ---- folded init (block 0,0): zero h ping 0 (fp16) and padded flags ----
    if (blockIdx.x == 0 && blockIdx.y == 0) {
#pragma unroll
        for (int it = 0; it < 16; ++it) {
            int i = tid + it * 256;
            g_hf[0][i] = make_uint2(0u, 0u);
        }
#pragma unroll
        for (int it = 0; it < 16; ++it)
            g_flags[tid + it * 256] = 0;
    }

    if (tid < 128) bias_sm[tid] = bi[gn0 + tid] + bh[gn0 + tid];

    const float* asrc[4];
    const float* bsrc[4];
    uint32_t adst[4], bdst[4];
#pragma unroll
    for (int it = 0; it < 4; ++it) {
        int aidx = tid + it * 256;
        int row = aidx >> 3, q = aidx & 7;
        int m = gm0 + row;
        asrc[it] = x + ((size_t)(m & 31) * TT + (m >> 5)) * II + q * 4;
        adst[it] = row * P1_ROWB + q * 8;
        bsrc[it] = Wi + (size_t)(gn0 + row) * II + q * 4;
        bdst[it] = row * P1_ROWB + q * 8;
    }

    float acc[4][4][4];
#pragma unroll
    for (int a = 0; a < 4; ++a)
#pragma unroll
        for (int b = 0; b < 4; ++b)
#pragma unroll
            for (int c = 0; c < 4; ++c) acc[a][b][c] = 0.0f;

    float4 v[8];
#pragma unroll
    for (int it = 0; it < 4; ++it) {
        v[it]     = *reinterpret_cast<const float4*>(asrc[it]);
        v[4 + it] = *reinterpret_cast<const float4*>(bsrc[it]);
    }

    for (int kt = 0; kt < 16; ++kt) {
        char* buf = sm + (kt & 1) * P1_BUFB;
#pragma unroll
        for (int it = 0; it < 8; ++it) {
            float4 w = v[it];
            uint32_t h01, l01, h23, l23;
            split_pair(w.x, w.y, h01, l01);
            split_pair(w.z, w.w, h23, l23);
            char* dhi = buf + ((it < 4) ? adst[it] : (2 * P1_OPB + bdst[it - 4]));
            *reinterpret_cast<uint2*>(dhi) = make_uint2(h01, h23);
            *reinterpret_cast<uint2*>(dhi + P1_OPB) = make_uint2(l01, l23);
        }
        __syncthreads();

        if (kt < 15) {
            int ko = (kt + 1) * 32;
#pragma unroll
            for (int it = 0; it < 4; ++it) {
                v[it]     = *reinterpret_cast<const float4*>(asrc[it] + ko);
                v[4 + it] = *reinterpret_cast<const float4*>(bsrc[it] + ko);
            }
        }

        const char* Ah = buf;
        const char* Al = buf + P1_OPB;
        const char* Bh = buf + 2 * P1_OPB;
        const char* Bl = buf + 3 * P1_OPB;

#pragma unroll
        for (int ks = 0; ks < 2; ++ks) {
            const int kb = ks * 32 + 4 * t4;
            uint32_t bhf[4][2], blf[4][2];
#pragma unroll
            for (int nt = 0; nt < 4; ++nt) {
                int n = wn * 32 + nt * 8 + g;
                const char* ph = Bh + n * P1_ROWB + kb;
                const char* pl = Bl + n * P1_ROWB + kb;
                bhf[nt][0] = *reinterpret_cast<const uint32_t*>(ph);
                bhf[nt][1] = *reinterpret_cast<const uint32_t*>(ph + 16);
                blf[nt][0] = *reinterpret_cast<const uint32_t*>(pl);
                blf[nt][1] = *reinterpret_cast<const uint32_t*>(pl + 16);
            }
#pragma unroll
            for (int mt = 0; mt < 4; ++mt) {
                int r = wm * 64 + mt * 16 + g;
                const char* ph = Ah + r * P1_ROWB + kb;
                const char* pl = Al + r * P1_ROWB + kb;
                uint32_t ahf[4], alf[4];
                ahf[0] = *reinterpret_cast<const uint32_t*>(ph);
                ahf[1] = *reinterpret_cast<const uint32_t*>(ph + 8 * P1_ROWB);
                ahf[2] = *reinterpret_cast<const uint32_t*>(ph + 16);
                ahf[3] = *reinterpret_cast<const uint32_t*>(ph + 8 * P1_ROWB + 16);
                alf[0] = *reinterpret_cast<const uint32_t*>(pl);
                alf[1] = *reinterpret_cast<const uint32_t*>(pl + 8 * P1_ROWB);
                alf[2] = *reinterpret_cast<const uint32_t*>(pl + 16);
                alf[3] = *reinterpret_cast<const uint32_t*>(pl + 8 * P1_ROWB + 16);
#pragma unroll
                for (int nt = 0; nt < 4; ++nt) {
                    mma_bf16(acc[mt][nt], ahf, bhf[nt]);
                    mma_bf16(acc[mt][nt], ahf, blf[nt]);
                    mma_bf16(acc[mt][nt], alf, bhf[nt]);
                }
            }
        }
        __syncthreads();
    }

    // ---- epilogue: stage [tloc][n][b] in SMEM, then coalesced STG ----
    float* stage = reinterpret_cast<float*>(sm);
#pragma unroll
    for (int mt = 0; mt < 4; ++mt) {
        int lm0 = wm * 64 + mt * 16 + g;
        int lm1 = lm0 + 8;
        int tl0 = lm0 >> 5, bb0 = lm0 & 31;
        int tl1 = lm1 >> 5, bb1 = lm1 & 31;
#pragma unroll
        for (int nt = 0; nt < 4; ++nt) {
            int nl = wn * 32 + nt * 8 + 2 * t4;
            float bv0 = bias_sm[nl], bv1 = bias_sm[nl + 1];
            stage[(tl0 * 128 + nl) * EPI_STRIDE + bb0]       = acc[mt][nt][0] + bv0;
            stage[(tl0 * 128 + nl + 1) * EPI_STRIDE + bb0]   = acc[mt][nt][1] + bv1;
            stage[(tl1 * 128 + nl) * EPI_STRIDE + bb1]       = acc[mt][nt][2] + bv0;
            stage[(tl1 * 128 + nl + 1) * EPI_STRIDE + bb1]   = acc[mt][nt][3] + bv1;
        }
    }
    __syncthreads();

    const size_t tbase = (size_t)(gm0 >> 5);
#pragma unroll
    for (int it = 0; it < 16; ++it) {
        int i = tid + it * 256;
        int row = i >> 3;
        int q = i & 7;
        int tloc = row >> 7, n = row & 127;
        float4 val = *reinterpret_cast<const float4*>(&stage[row * EPI_STRIDE + q * 4]);
        float* dst = g_gx + ((tbase + tloc) * GG + gn0 + n) * 32 + q * 4;
        *reinterpret_cast<float4*>(dst) = val;
    }
}

// ============================================================================
// Phase 2: persistent scan. 128 CTAs x 4 hidden units; fp16x2 recurrent GEMM.
// ============================================================================
#define HW_SLAB 4608                          // per-warp: 32 b * 144B (fp16 h)
#define OFF_PART (8 * HW_SLAB)                // 36864
#define PART_SLABW (16 * 36)                  // 576 floats per warp slab
#define OFF_HROW (OFF_PART + 8 * PART_SLABW * 4)   // 55296
#define SCAN_SMEM (OFF_HROW + 32 * 5 * 4 + 64)     // 56000

__global__ __launch_bounds__(256, 1) void lstm_scan_tc(
    const float* __restrict__ Wh,
    float* __restrict__ y, float* __restrict__ hfin, float* __restrict__ cfin)
{
    extern __shared__ char sm[];
    const int tid = threadIdx.x;
    const int wid = tid >> 5;
    const int lane = tid & 31;
    const int g = lane >> 2;
    const int t4 = lane & 3;
    const int J0 = blockIdx.x * 4;
    const int kb = wid * 64;

    // ---- preload Wh A-fragments (fp16 hi/lo) into registers, once ----
    uint32_t ahf[4][4], alf[4][4];
    {
        const int grow0 = (g >> 2) * 512 + J0 + (g & 3);
        const int grow1 = grow0 + 1024;
#pragma unroll
        for (int ks = 0; ks < 4; ++ks) {
            int k0 = kb + ks * 16 + 2 * t4;
            float2 w00 = *reinterpret_cast<const float2*>(&Wh[(size_t)grow0 * HH + k0]);
            float2 w10 = *reinterpret_cast<const float2*>(&Wh[(size_t)grow1 * HH + k0]);
            float2 w01 = *reinterpret_cast<const float2*>(&Wh[(size_t)grow0 * HH + k0 + 8]);
            float2 w11 = *reinterpret_cast<const float2*>(&Wh[(size_t)grow1 * HH + k0 + 8]);
            split_pair_f16(w00.x, w00.y, ahf[ks][0], alf[ks][0]);
            split_pair_f16(w10.x, w10.y, ahf[ks][1], alf[ks][1]);
            split_pair_f16(w01.x, w01.y, ahf[ks][2], alf[ks][2]);
            split_pair_f16(w11.x, w11.y, ahf[ks][3], alf[ks][3]);
        }
    }

    char* wslab = sm + wid * HW_SLAB;
    const int jj = tid >> 5;                 // valid for tid<128 (0..3)
    const int b = tid & 31;

    float c_reg = 0.0f, h_last = 0.0f;

    for (int t = 0; t < TT; ++t) {
        const int p = t & 1;

        // gx prefetch (coalesced; in flight during the wait)
        const float* gxp = g_gx + ((size_t)t * GG + J0 + jj) * 32 + b;
        float gx0 = 0.f, gx1 = 0.f, gx2 = 0.f, gx3 = 0.f;
        if (tid < 128) {
            gx0 = gxp[0];
            gx1 = gxp[512 * 32];
            gx2 = gxp[1024 * 32];
            gx3 = gxp[1536 * 32];
        }

        // ---- warp 0 polls 128 padded flags (acquire, no backoff) ----
        if (t > 0) {
            if (wid == 0) {
                for (;;) {
                    int f0 = ldflag_acq(&g_flags[lane * 32]);
                    int f1 = ldflag_acq(&g_flags[(lane + 32) * 32]);
                    int f2 = ldflag_acq(&g_flags[(lane + 64) * 32]);
                    int f3 = ldflag_acq(&g_flags[(lane + 96) * 32]);
                    if (__all_sync(0xFFFFFFFFu,
                                   (f0 >= t) && (f1 >= t) && (f2 >= t) && (f3 >= t)))
                        break;
                }
            }
            __syncthreads();
        }

        // ---- per-warp h slice copy (fp16, L2 .cg): k-chunk [kb,kb+64) ----
        const uint4* __restrict__ src = reinterpret_cast<const uint4*>(&g_hf[p][0]);
        // uint4 index: b*64 + j/8 (8 fp16 per uint4)
#pragma unroll
        for (int it = 0; it < 8; ++it) {
            int idx = lane + it * 32;          // 0..255
            int bb = idx >> 3, j = idx & 7;
            uint4 val = __ldcg(&src[bb * 64 + wid * 8 + j]);
            *reinterpret_cast<uint4*>(wslab + bb * 144 + j * 16) = val;
        }
        __syncwarp();

        // ---- MMA: 16 gate rows x 32 batches over warp k-chunk, fp16x2 ----
        float acc[4][4];
#pragma unroll
        for (int nt = 0; nt < 4; ++nt)
#pragma unroll
            for (int c = 0; c < 4; ++c) acc[nt][c] = 0.0f;

#pragma unroll
        for (int ks = 0; ks < 4; ++ks) {
            uint32_t bf[4][2];
#pragma unroll
            for (int nt = 0; nt < 4; ++nt) {
                const char* ph = wslab + (nt * 8 + g) * 144 + (ks * 8 + t4) * 4;
                bf[nt][0] = *reinterpret_cast<const uint32_t*>(ph);
                bf[nt][1] = *reinterpret_cast<const uint32_t*>(ph + 16);
            }
#pragma unroll
            for (int nt = 0; nt < 4; ++nt) {
                mma_f16(acc[nt], ahf[ks], bf[nt]);
                mma_f16(acc[nt], alf[ks], bf[nt]);
            }
        }

        // ---- partials to SMEM ----
        {
            float* slab = reinterpret_cast<float*>(sm + OFF_PART) + wid * PART_SLABW;
#pragma unroll
            for (int nt = 0; nt < 4; ++nt) {
                int n = nt * 8 + 2 * t4;
                *reinterpret_cast<float2*>(&slab[g * 36 + n]) =
                    make_float2(acc[nt][0], acc[nt][1]);
                *reinterpret_cast<float2*>(&slab[(g + 8) * 36 + n]) =
                    make_float2(acc[nt][2], acc[nt][3]);
            }
        }
        __syncthreads();

        // ---- fused reduce + gate math: thread (jj, b), tid<128 ----
        if (tid < 128) {
            const float* pbase = reinterpret_cast<const float*>(sm + OFF_PART);
            float gate[4] = {gx0, gx1, gx2, gx3};
#pragma unroll
            for (int q = 0; q < 4; ++q) {
                const int m = q * 4 + jj;
#pragma unroll
                for (int w = 0; w < 8; ++w)
                    gate[q] += pbase[w * PART_SLABW + m * 36 + b];
            }
            float cn = sigf(gate[1]) * c_reg + sigf(gate[0]) * tanh_fast(gate[2]);
            float hn = sigf(gate[3]) * tanh_fast(cn);
            c_reg = cn;
            h_last = hn;
            reinterpret_cast<float*>(sm + OFF_HROW)[b * 5 + jj] = hn;
        }
        __syncthreads();

        // ---- writer warp 0: h -> global fp16; fence; publish; THEN y ----
        if (tid < 32) {
            const float* hr = reinterpret_cast<const float*>(sm + OFF_HROW) + tid * 5;
            float h0 = hr[0], h1 = hr[1], h2 = hr[2], h3 = hr[3];
            uint32_t p01 = pack_f16(h0, h1);
            uint32_t p23 = pack_f16(h2, h3);
            g_hf[p ^ 1][tid * 128 + blockIdx.x] = make_uint2(p01, p23);
            __syncwarp();
            if (tid == 0 && t < TT - 1) {
                __threadfence();                      // drain h stores to L2
                g_flags[blockIdx.x * 32] = t + 1;     // publish
            }
            // y after publish (not consumer-visible, off the critical path)
            float* yp = y + ((size_t)tid * TT + t) * HH + J0;
            *reinterpret_cast<float4*>(yp) = make_float4(h0, h1, h2, h3);
        }
    }

    if (tid < 128) {
        hfin[(size_t)b * HH + J0 + jj] = h_last;
        cfin[(size_t)b * HH + J0 + jj] = c_reg;
    }
}

// ============================================================================
// launch (2 kernels; init folded into gemm)
// ============================================================================
extern "C" void kernel_launch(void* const* d_in, const int* in_sizes, int n_in,
                              void* d_out, int out_size) {
    const float* x  = (const float*)d_in[0];
    const float* Wi = (const float*)d_in[1];
    const float* bi = (const float*)d_in[2];
    const float* Wh = (const float*)d_in[3];
    const float* bh = (const float*)d_in[4];

    float* y    = (float*)d_out;
    float* hfin = y + (size_t)BB * TT * HH;
    float* cfin = hfin + (size_t)BB * HH;

    cudaFuncSetAttribute(gemm_gx_tc,
                         cudaFuncAttributeMaxDynamicSharedMemorySize, P1_SMEM);
    cudaFuncSetAttribute(lstm_scan_tc,
                         cudaFuncAttributeMaxDynamicSharedMemorySize, SCAN_SMEM);

    gemm_gx_tc<<<dim3(16, 512), 256, P1_SMEM>>>(x, Wi, bi, bh);
    lstm_scan_tc<<<NCTA2, 256, SCAN_SMEM>>>(Wh, y, hfin, cfin);
}

// round 11
// speedup vs baseline: 2.9554x; 1.4184x over previous
#include <cuda_runtime.h>
#include <cuda_bf16.h>
#include <cuda_fp16.h>
#include <cstdint>

// ============================================================================
// CustomLSTM: B=32, T=2048, I=512, H=512 (4H=2048)
// Phase 1: gx = x@Wi^T + bi + bh  -- bf16x3 HMMA, 128x128 tiles, SMEM-staged
//          transposed epilogue -> gx[t][g][b]. Init folded into block (0,0).
// Phase 2: persistent scan, 128 CTAs x 4 hidden units, fp16x2 HMMA.
//          PER-WARP producer waits: warp w needs k-chunk [64w,64w+64) which
//          is produced by CTAs 16w..16w+15 only -> each warp polls just its
//          16 producer flags and starts copy+MMA immediately (stragglers
//          overlap). Union over warps = all CTAs => ping-pong safety holds.
// NOTE: harness PTX target is compute_103 (no 'a') -> tcgen05 unavailable.
// ============================================================================

#define TT 2048
#define BB 32
#define II 512
#define HH 512
#define GG 2048

#define NCTA2 128

// ---------------- device scratch ----------------
__device__ float g_gx[(size_t)TT * GG * BB];     // [t][g][b]  512 MB
__device__ uint2 g_hf[2][BB * 128];              // ping x [b][j/4] fp16 h (32KB)
__device__ int   g_flags[NCTA2 * 32];            // one flag per 128B line

__device__ __forceinline__ float sigf(float x) { return 1.0f / (1.0f + __expf(-x)); }
__device__ __forceinline__ float tanh_fast(float x) {
    float r;
    asm("tanh.approx.f32 %0, %1;" : "=f"(r) : "f"(x));
    return r;
}
__device__ __forceinline__ int ldflag_acq(const int* p) {
    int v;
    asm volatile("ld.acquire.gpu.global.b32 %0, [%1];" : "=r"(v) : "l"(p) : "memory");
    return v;
}

// ---- bf16 split (phase 1) ----
__device__ __forceinline__ void split_pair(float f0, float f1, uint32_t& hi2, uint32_t& lo2) {
    uint32_t h;
    asm("cvt.rn.bf16x2.f32 %0, %1, %2;" : "=r"(h) : "f"(f1), "f"(f0));
    float h0 = __uint_as_float(h << 16);
    float h1 = __uint_as_float(h & 0xFFFF0000u);
    asm("cvt.rn.bf16x2.f32 %0, %1, %2;" : "=r"(lo2) : "f"(f1 - h1), "f"(f0 - h0));
    hi2 = h;
}

// ---- fp16 split (scan Wh) ----
__device__ __forceinline__ void split_pair_f16(float f0, float f1, uint32_t& hi2, uint32_t& lo2) {
    uint32_t h;
    asm("cvt.rn.f16x2.f32 %0, %1, %2;" : "=r"(h) : "f"(f1), "f"(f0));
    __half2 hh = *reinterpret_cast<__half2*>(&h);
    float h0 = __low2float(hh), h1 = __high2float(hh);
    asm("cvt.rn.f16x2.f32 %0, %1, %2;" : "=r"(lo2) : "f"(f1 - h1), "f"(f0 - h0));
    hi2 = h;
}
__device__ __forceinline__ uint32_t pack_f16(float f0, float f1) {
    uint32_t h;
    asm("cvt.rn.f16x2.f32 %0, %1, %2;" : "=r"(h) : "f"(f1), "f"(f0));
    return h;
}

__device__ __forceinline__ void mma_bf16(float* d, const uint32_t* a, const uint32_t* b) {
    asm volatile(
        "mma.sync.aligned.m16n8k16.row.col.f32.bf16.bf16.f32 "
        "{%0,%1,%2,%3}, {%4,%5,%6,%7}, {%8,%9}, {%0,%1,%2,%3};"
        : "+f"(d[0]), "+f"(d[1]), "+f"(d[2]), "+f"(d[3])
        : "r"(a[0]), "r"(a[1]), "r"(a[2]), "r"(a[3]), "r"(b[0]), "r"(b[1]));
}
__device__ __forceinline__ void mma_f16(float* d, const uint32_t* a, const uint32_t* b) {
    asm volatile(
        "mma.sync.aligned.m16n8k16.row.col.f32.f16.f16.f32 "
        "{%0,%1,%2,%3}, {%4,%5,%6,%7}, {%8,%9}, {%0,%1,%2,%3};"
        : "+f"(d[0]), "+f"(d[1]), "+f"(d[2]), "+f"(d[3])
        : "r"(a[0]), "r"(a[1]), "r"(a[2]), "r"(a[3]), "r"(b[0]), "r"(b[1]));
}

// ============================================================================
// Phase 1: bf16x3 HMMA GEMM; SMEM-staged transposed epilogue; init fold
// ============================================================================
#define P1_ROWB 80
#define P1_OPB  (128 * P1_ROWB)
#define P1_BUFB (4 * P1_OPB)
#define P1_SMEM (2 * P1_BUFB + 512)
#define EPI_STRIDE 36

__global__ __launch_bounds__(256, 2) void gemm_gx_tc(
    const float* __restrict__ x, const float* __restrict__ Wi,
    const float* __restrict__ bi, const float* __restrict__ bh)
{
    extern __shared__ char sm[];
    float* bias_sm = reinterpret_cast<float*>(sm + 2 * P1_BUFB);

    const int tid = threadIdx.x;
    const int wid = tid >> 5;
    const int lane = tid & 31;
    const int g = lane >> 2;
    const int t4 = lane & 3;
    const int wm = wid >> 2;
    const int wn = wid & 3;

    const int gn0 = blockIdx.x * 128;
    const int gm0 = blockIdx.y * 128;

    // ---- folded init (block 0,0): zero h ping 0 (fp16) and padded flags ----
    if (blockIdx.x == 0 && blockIdx.y == 0) {
#pragma unroll
        for (int it = 0; it < 16; ++it) {
            int i = tid + it * 256;
            g_hf[0][i] = make_uint2(0u, 0u);
        }
#pragma unroll
        for (int it = 0; it < 16; ++it)
            g_flags[tid + it * 256] = 0;
    }

    if (tid < 128) bias_sm[tid] = bi[gn0 + tid] + bh[gn0 + tid];

    const float* asrc[4];
    const float* bsrc[4];
    uint32_t adst[4], bdst[4];
#pragma unroll
    for (int it = 0; it < 4; ++it) {
        int aidx = tid + it * 256;
        int row = aidx >> 3, q = aidx & 7;
        int m = gm0 + row;
        asrc[it] = x + ((size_t)(m & 31) * TT + (m >> 5)) * II + q * 4;
        adst[it] = row * P1_ROWB + q * 8;
        bsrc[it] = Wi + (size_t)(gn0 + row) * II + q * 4;
        bdst[it] = row * P1_ROWB + q * 8;
    }

    float acc[4][4][4];
#pragma unroll
    for (int a = 0; a < 4; ++a)
#pragma unroll
        for (int b = 0; b < 4; ++b)
#pragma unroll
            for (int c = 0; c < 4; ++c) acc[a][b][c] = 0.0f;

    float4 v[8];
#pragma unroll
    for (int it = 0; it < 4; ++it) {
        v[it]     = *reinterpret_cast<const float4*>(asrc[it]);
        v[4 + it] = *reinterpret_cast<const float4*>(bsrc[it]);
    }

    for (int kt = 0; kt < 16; ++kt) {
        char* buf = sm + (kt & 1) * P1_BUFB;
#pragma unroll
        for (int it = 0; it < 8; ++it) {
            float4 w = v[it];
            uint32_t h01, l01, h23, l23;
            split_pair(w.x, w.y, h01, l01);
            split_pair(w.z, w.w, h23, l23);
            char* dhi = buf + ((it < 4) ? adst[it] : (2 * P1_OPB + bdst[it - 4]));
            *reinterpret_cast<uint2*>(dhi) = make_uint2(h01, h23);
            *reinterpret_cast<uint2*>(dhi + P1_OPB) = make_uint2(l01, l23);
        }
        __syncthreads();

        if (kt < 15) {
            int ko = (kt + 1) * 32;
#pragma unroll
            for (int it = 0; it < 4; ++it) {
                v[it]     = *reinterpret_cast<const float4*>(asrc[it] + ko);
                v[4 + it] = *reinterpret_cast<const float4*>(bsrc[it] + ko);
            }
        }

        const char* Ah = buf;
        const char* Al = buf + P1_OPB;
        const char* Bh = buf + 2 * P1_OPB;
        const char* Bl = buf + 3 * P1_OPB;

#pragma unroll
        for (int ks = 0; ks < 2; ++ks) {
            const int kb = ks * 32 + 4 * t4;
            uint32_t bhf[4][2], blf[4][2];
#pragma unroll
            for (int nt = 0; nt < 4; ++nt) {
                int n = wn * 32 + nt * 8 + g;
                const char* ph = Bh + n * P1_ROWB + kb;
                const char* pl = Bl + n * P1_ROWB + kb;
                bhf[nt][0] = *reinterpret_cast<const uint32_t*>(ph);
                bhf[nt][1] = *reinterpret_cast<const uint32_t*>(ph + 16);
                blf[nt][0] = *reinterpret_cast<const uint32_t*>(pl);
                blf[nt][1] = *reinterpret_cast<const uint32_t*>(pl + 16);
            }
#pragma unroll
            for (int mt = 0; mt < 4; ++mt) {
                int r = wm * 64 + mt * 16 + g;
                const char* ph = Ah + r * P1_ROWB + kb;
                const char* pl = Al + r * P1_ROWB + kb;
                uint32_t ahf[4], alf[4];
                ahf[0] = *reinterpret_cast<const uint32_t*>(ph);
                ahf[1] = *reinterpret_cast<const uint32_t*>(ph + 8 * P1_ROWB);
                ahf[2] = *reinterpret_cast<const uint32_t*>(ph + 16);
                ahf[3] = *reinterpret_cast<const uint32_t*>(ph + 8 * P1_ROWB + 16);
                alf[0] = *reinterpret_cast<const uint32_t*>(pl);
                alf[1] = *reinterpret_cast<const uint32_t*>(pl + 8 * P1_ROWB);
                alf[2] = *reinterpret_cast<const uint32_t*>(pl + 16);
                alf[3] = *reinterpret_cast<const uint32_t*>(pl + 8 * P1_ROWB + 16);
#pragma unroll
                for (int nt = 0; nt < 4; ++nt) {
                    mma_bf16(acc[mt][nt], ahf, bhf[nt]);
                    mma_bf16(acc[mt][nt], ahf, blf[nt]);
                    mma_bf16(acc[mt][nt], alf, bhf[nt]);
                }
            }
        }
        __syncthreads();
    }

    // ---- epilogue: stage [tloc][n][b] in SMEM, then coalesced STG ----
    float* stage = reinterpret_cast<float*>(sm);
#pragma unroll
    for (int mt = 0; mt < 4; ++mt) {
        int lm0 = wm * 64 + mt * 16 + g;
        int lm1 = lm0 + 8;
        int tl0 = lm0 >> 5, bb0 = lm0 & 31;
        int tl1 = lm1 >> 5, bb1 = lm1 & 31;
#pragma unroll
        for (int nt = 0; nt < 4; ++nt) {
            int nl = wn * 32 + nt * 8 + 2 * t4;
            float bv0 = bias_sm[nl], bv1 = bias_sm[nl + 1];
            stage[(tl0 * 128 + nl) * EPI_STRIDE + bb0]       = acc[mt][nt][0] + bv0;
            stage[(tl0 * 128 + nl + 1) * EPI_STRIDE + bb0]   = acc[mt][nt][1] + bv1;
            stage[(tl1 * 128 + nl) * EPI_STRIDE + bb1]       = acc[mt][nt][2] + bv0;
            stage[(tl1 * 128 + nl + 1) * EPI_STRIDE + bb1]   = acc[mt][nt][3] + bv1;
        }
    }
    __syncthreads();

    const size_t tbase = (size_t)(gm0 >> 5);
#pragma unroll
    for (int it = 0; it < 16; ++it) {
        int i = tid + it * 256;
        int row = i >> 3;
        int q = i & 7;
        int tloc = row >> 7, n = row & 127;
        float4 val = *reinterpret_cast<const float4*>(&stage[row * EPI_STRIDE + q * 4]);
        float* dst = g_gx + ((tbase + tloc) * GG + gn0 + n) * 32 + q * 4;
        *reinterpret_cast<float4*>(dst) = val;
    }
}

// ============================================================================
// Phase 2: persistent scan. 128 CTAs x 4 hidden units; fp16x2 recurrent GEMM;
//          per-warp producer-set flag waits.
// ============================================================================
#define HW_SLAB 4608                          // per-warp: 32 b * 144B (fp16 h)
#define OFF_PART (8 * HW_SLAB)                // 36864
#define PART_SLABW (16 * 36)                  // 576 floats per warp slab
#define OFF_HROW (OFF_PART + 8 * PART_SLABW * 4)   // 55296
#define SCAN_SMEM (OFF_HROW + 32 * 5 * 4 + 64)     // 56000

__global__ __launch_bounds__(256, 1) void lstm_scan_tc(
    const float* __restrict__ Wh,
    float* __restrict__ y, float* __restrict__ hfin, float* __restrict__ cfin)
{
    extern __shared__ char sm[];
    const int tid = threadIdx.x;
    const int wid = tid >> 5;
    const int lane = tid & 31;
    const int g = lane >> 2;
    const int t4 = lane & 3;
    const int J0 = blockIdx.x * 4;
    const int kb = wid * 64;

    // ---- preload Wh A-fragments (fp16 hi/lo) into registers, once ----
    uint32_t ahf[4][4], alf[4][4];
    {
        const int grow0 = (g >> 2) * 512 + J0 + (g & 3);
        const int grow1 = grow0 + 1024;
#pragma unroll
        for (int ks = 0; ks < 4; ++ks) {
            int k0 = kb + ks * 16 + 2 * t4;
            float2 w00 = *reinterpret_cast<const float2*>(&Wh[(size_t)grow0 * HH + k0]);
            float2 w10 = *reinterpret_cast<const float2*>(&Wh[(size_t)grow1 * HH + k0]);
            float2 w01 = *reinterpret_cast<const float2*>(&Wh[(size_t)grow0 * HH + k0 + 8]);
            float2 w11 = *reinterpret_cast<const float2*>(&Wh[(size_t)grow1 * HH + k0 + 8]);
            split_pair_f16(w00.x, w00.y, ahf[ks][0], alf[ks][0]);
            split_pair_f16(w10.x, w10.y, ahf[ks][1], alf[ks][1]);
            split_pair_f16(w01.x, w01.y, ahf[ks][2], alf[ks][2]);
            split_pair_f16(w11.x, w11.y, ahf[ks][3], alf[ks][3]);
        }
    }

    char* wslab = sm + wid * HW_SLAB;
    const int jj = tid >> 5;                 // valid for tid<128 (0..3)
    const int b = tid & 31;

    // per-warp producer flag: warp w consumes h from CTAs [16w, 16w+16)
    const int* my_flag = &g_flags[(wid * 16 + (lane & 15)) * 32];

    float c_reg = 0.0f, h_last = 0.0f;

    for (int t = 0; t < TT; ++t) {
        const int p = t & 1;

        // gx prefetch (coalesced; in flight during the wait)
        const float* gxp = g_gx + ((size_t)t * GG + J0 + jj) * 32 + b;
        float gx0 = 0.f, gx1 = 0.f, gx2 = 0.f, gx3 = 0.f;
        if (tid < 128) {
            gx0 = gxp[0];
            gx1 = gxp[512 * 32];
            gx2 = gxp[1024 * 32];
            gx3 = gxp[1536 * 32];
        }

        // ---- per-warp wait: only this warp's 16 producer CTAs ----
        if (t > 0) {
            int f;
            do {
                f = ldflag_acq(my_flag);
            } while (!__all_sync(0xFFFFFFFFu, f >= t));
        }

        // ---- per-warp h slice copy (fp16, L2 .cg): k-chunk [kb,kb+64) ----
        const uint4* __restrict__ src = reinterpret_cast<const uint4*>(&g_hf[p][0]);
#pragma unroll
        for (int it = 0; it < 8; ++it) {
            int idx = lane + it * 32;          // 0..255
            int bb = idx >> 3, j = idx & 7;
            uint4 val = __ldcg(&src[bb * 64 + wid * 8 + j]);
            *reinterpret_cast<uint4*>(wslab + bb * 144 + j * 16) = val;
        }
        __syncwarp();

        // ---- MMA: 16 gate rows x 32 batches over warp k-chunk, fp16x2 ----
        float acc[4][4];
#pragma unroll
        for (int nt = 0; nt < 4; ++nt)
#pragma unroll
            for (int c = 0; c < 4; ++c) acc[nt][c] = 0.0f;

#pragma unroll
        for (int ks = 0; ks < 4; ++ks) {
            uint32_t bf[4][2];
#pragma unroll
            for (int nt = 0; nt < 4; ++nt) {
                const char* ph = wslab + (nt * 8 + g) * 144 + (ks * 8 + t4) * 4;
                bf[nt][0] = *reinterpret_cast<const uint32_t*>(ph);
                bf[nt][1] = *reinterpret_cast<const uint32_t*>(ph + 16);
            }
#pragma unroll
            for (int nt = 0; nt < 4; ++nt) {
                mma_f16(acc[nt], ahf[ks], bf[nt]);
                mma_f16(acc[nt], alf[ks], bf[nt]);
            }
        }

        // ---- partials to SMEM ----
        {
            float* slab = reinterpret_cast<float*>(sm + OFF_PART) + wid * PART_SLABW;
#pragma unroll
            for (int nt = 0; nt < 4; ++nt) {
                int n = nt * 8 + 2 * t4;
                *reinterpret_cast<float2*>(&slab[g * 36 + n]) =
                    make_float2(acc[nt][0], acc[nt][1]);
                *reinterpret_cast<float2*>(&slab[(g + 8) * 36 + n]) =
                    make_float2(acc[nt][2], acc[nt][3]);
            }
        }
        __syncthreads();

        // ---- fused reduce + gate math: thread (jj, b), tid<128 ----
        if (tid < 128) {
            const float* pbase = reinterpret_cast<const float*>(sm + OFF_PART);
            float gate[4] = {gx0, gx1, gx2, gx3};
#pragma unroll
            for (int q = 0; q < 4; ++q) {
                const int m = q * 4 + jj;
#pragma unroll
                for (int w = 0; w < 8; ++w)
                    gate[q] += pbase[w * PART_SLABW + m * 36 + b];
            }
            float cn = sigf(gate[1]) * c_reg + sigf(gate[0]) * tanh_fast(gate[2]);
            float hn = sigf(gate[3]) * tanh_fast(cn);
            c_reg = cn;
            h_last = hn;
            reinterpret_cast<float*>(sm + OFF_HROW)[b * 5 + jj] = hn;
        }
        __syncthreads();

        // ---- writer warp 0: h -> global fp16; fence; publish; THEN y ----
        if (tid < 32) {
            const float* hr = reinterpret_cast<const float*>(sm + OFF_HROW) + tid * 5;
            float h0 = hr[0], h1 = hr[1], h2 = hr[2], h3 = hr[3];
            uint32_t p01 = pack_f16(h0, h1);
            uint32_t p23 = pack_f16(h2, h3);
            g_hf[p ^ 1][tid * 128 + blockIdx.x] = make_uint2(p01, p23);
            __syncwarp();
            if (tid == 0 && t < TT - 1) {
                __threadfence();                      // drain h stores to L2
                g_flags[blockIdx.x * 32] = t + 1;     // publish
            }
            // y after publish (not consumer-visible, off the critical path)
            float* yp = y + ((size_t)tid * TT + t) * HH + J0;
            *reinterpret_cast<float4*>(yp) = make_float4(h0, h1, h2, h3);
        }
    }

    if (tid < 128) {
        hfin[(size_t)b * HH + J0 + jj] = h_last;
        cfin[(size_t)b * HH + J0 + jj] = c_reg;
    }
}

// ============================================================================
// launch (2 kernels; init folded into gemm)
// ============================================================================
extern "C" void kernel_launch(void* const* d_in, const int* in_sizes, int n_in,
                              void* d_out, int out_size) {
    const float* x  = (const float*)d_in[0];
    const float* Wi = (const float*)d_in[1];
    const float* bi = (const float*)d_in[2];
    const float* Wh = (const float*)d_in[3];
    const float* bh = (const float*)d_in[4];

    float* y    = (float*)d_out;
    float* hfin = y + (size_t)BB * TT * HH;
    float* cfin = hfin + (size_t)BB * HH;

    cudaFuncSetAttribute(gemm_gx_tc,
                         cudaFuncAttributeMaxDynamicSharedMemorySize, P1_SMEM);
    cudaFuncSetAttribute(lstm_scan_tc,
                         cudaFuncAttributeMaxDynamicSharedMemorySize, SCAN_SMEM);

    gemm_gx_tc<<<dim3(16, 512), 256, P1_SMEM>>>(x, Wi, bi, bh);
    lstm_scan_tc<<<NCTA2, 256, SCAN_SMEM>>>(Wh, y, hfin, cfin);
}